// round 1
// baseline (speedup 1.0000x reference)
#include <cuda_runtime.h>
#include <math.h>

#define N_NODES 819200
#define N_EDGES 6553600
#define BATCH   16384
#define NPG     50
#define NPAIRC  1225
#define DIN     10
#define HH      32
#define BN_EPS  1e-5f

// ---------------- scratch (static device globals; no allocation) ----------------
__device__ float g_agg0 [N_NODES * 12];      // layer0 edge agg (10 used, pad 12 for 16B align)
__device__ float g_h1   [N_NODES * 32];      // h (pre-BN post-relu) / reused for h3
__device__ float g_h2   [N_NODES * 32];      // layer0 output / reused for h4
__device__ float g_agg32[N_NODES * 32];      // layer1 edge agg
__device__ double g_stats[128];              // [0:32) sum0 [32:64) sq0 [64:96) sum1 [96:128) sq1
__device__ float g_W2eff [1024], g_b2eff [32];
__device__ float g_W2eff2[1024], g_b2eff2[32];
__device__ float g_wT[32 * NPAIRC];          // (W1[:,2p]-W1[:,2p+1]) transposed: [k][p]
__device__ float g_db[NPAIRC];
__device__ int   g_iu[NPAIRC], g_ju[NPAIRC];
__device__ float g_xg[BATCH * 32];
__device__ float g_dT[32 * BATCH];           // decoder activations, transposed [k][b]
__device__ unsigned char g_vals[(size_t)BATCH * NPAIRC];

// ---------------- zero scratch ----------------
__global__ void k_zero() {
    size_t i = (size_t)blockIdx.x * blockDim.x + threadIdx.x;
    const size_t n0 = (size_t)N_NODES * 12 / 4;
    const size_t n1 = (size_t)N_NODES * 32 / 4;
    float4 z = make_float4(0.f, 0.f, 0.f, 0.f);
    if (i < n0)             ((float4*)g_agg0)[i] = z;
    else if (i < n0 + n1)   ((float4*)g_agg32)[i - n0] = z;
    if (i < 128) g_stats[i] = 0.0;
}

// ---------------- edge scatter, layer0 (10 floats/edge) ----------------
__global__ void k_scatter0(const int* __restrict__ ei, const float* __restrict__ x) {
    int e = blockIdx.x * blockDim.x + threadIdx.x;
    if (e >= N_EDGES) return;
    int s = ei[e];
    int t = ei[N_EDGES + e];
    const float2* xs = (const float2*)(x + (size_t)s * DIN);   // 40B*s -> 8B aligned
    float2 v0 = xs[0], v1 = xs[1], v2 = xs[2], v3 = xs[3], v4 = xs[4];
    float* base = g_agg0 + (size_t)t * 12;                     // 48B*t -> 16B aligned
    atomicAdd((float4*)base,       make_float4(v0.x, v0.y, v1.x, v1.y));
    atomicAdd((float4*)(base + 4), make_float4(v2.x, v2.y, v3.x, v3.y));
    atomicAdd((float2*)(base + 8), v4);
}

// ---------------- edge scatter, layer1 (32 floats/edge) ----------------
__global__ void k_scatter1(const int* __restrict__ ei) {
    int e = blockIdx.x * blockDim.x + threadIdx.x;
    if (e >= N_EDGES) return;
    int s = ei[e];
    int t = ei[N_EDGES + e];
    const float4* hr = (const float4*)(g_h2 + (size_t)s * 32);
    float4* ar = (float4*)(g_agg32 + (size_t)t * 32);
#pragma unroll
    for (int i = 0; i < 8; i++) atomicAdd(&ar[i], hr[i]);
}

// ---------------- layer0 input transform: h = relu((x+agg)@W1 + b1) ----------------
__global__ void k_gin0(const float* __restrict__ x, const float* __restrict__ W1,
                       const float* __restrict__ b1) {
    __shared__ float sW[DIN * 32];
    __shared__ float sb[32];
    int t = threadIdx.x;
    for (int i = t; i < DIN * 32; i += blockDim.x) sW[i] = W1[i];
    if (t < 32) sb[t] = b1[t];
    __syncthreads();
    int n = blockIdx.x * blockDim.x + t;
    if (n >= N_NODES) return;
    const float2* xr = (const float2*)(x + (size_t)n * DIN);
    const float*  ar = g_agg0 + (size_t)n * 12;
    float4 a0 = *(const float4*)ar;
    float4 a1 = *(const float4*)(ar + 4);
    float2 a2 = *(const float2*)(ar + 8);
    float2 x0 = xr[0], x1 = xr[1], x2 = xr[2], x3 = xr[3], x4 = xr[4];
    float s[DIN];
    s[0] = x0.x + a0.x; s[1] = x0.y + a0.y; s[2] = x1.x + a0.z; s[3] = x1.y + a0.w;
    s[4] = x2.x + a1.x; s[5] = x2.y + a1.y; s[6] = x3.x + a1.z; s[7] = x3.y + a1.w;
    s[8] = x4.x + a2.x; s[9] = x4.y + a2.y;
    float* o = g_h1 + (size_t)n * 32;
#pragma unroll 4
    for (int j = 0; j < 32; j++) {
        float acc = sb[j];
#pragma unroll
        for (int k = 0; k < DIN; k++) acc += s[k] * sW[k * 32 + j];
        o[j] = fmaxf(acc, 0.f);
    }
}

// ---------------- generic 32x32 layer: out = relu((in[+in2]) @ W + b) ----------------
template<bool HAS_ADD, bool TRANS_OUT>
__global__ void __launch_bounds__(256) k_linear32(
    const float* __restrict__ in, const float* __restrict__ in2,
    const float* __restrict__ W, const float* __restrict__ bias,
    float* __restrict__ out, int nrows, int ostride) {
    __shared__ float sW[1024];
    __shared__ float sb[32];
    int t = threadIdx.x;
    for (int i = t; i < 1024; i += blockDim.x) sW[i] = W[i];
    if (t < 32) sb[t] = bias[t];
    __syncthreads();
    int r = (blockIdx.x * blockDim.x + t) * 2;   // nrows always even here
    if (r >= nrows) return;
    float hA[32], hB[32];
    const float4* ia = (const float4*)(in + (size_t)r * 32);
    const float4* ib = (const float4*)(in + (size_t)(r + 1) * 32);
#pragma unroll
    for (int q = 0; q < 8; q++) {
        float4 v = ia[q];
        hA[4*q] = v.x; hA[4*q+1] = v.y; hA[4*q+2] = v.z; hA[4*q+3] = v.w;
        float4 w = ib[q];
        hB[4*q] = w.x; hB[4*q+1] = w.y; hB[4*q+2] = w.z; hB[4*q+3] = w.w;
    }
    if (HAS_ADD) {
        const float4* ja = (const float4*)(in2 + (size_t)r * 32);
        const float4* jb = (const float4*)(in2 + (size_t)(r + 1) * 32);
#pragma unroll
        for (int q = 0; q < 8; q++) {
            float4 v = ja[q];
            hA[4*q] += v.x; hA[4*q+1] += v.y; hA[4*q+2] += v.z; hA[4*q+3] += v.w;
            float4 w = jb[q];
            hB[4*q] += w.x; hB[4*q+1] += w.y; hB[4*q+2] += w.z; hB[4*q+3] += w.w;
        }
    }
#pragma unroll 2
    for (int j = 0; j < 32; j++) {
        float a = sb[j], b = sb[j];
#pragma unroll
        for (int k = 0; k < 32; k++) {
            float w = sW[k * 32 + j];
            a += hA[k] * w;
            b += hB[k] * w;
        }
        a = fmaxf(a, 0.f);
        b = fmaxf(b, 0.f);
        if (TRANS_OUT) {
            out[(size_t)j * ostride + r]     = a;
            out[(size_t)j * ostride + r + 1] = b;
        } else {
            out[(size_t)r * 32 + j]       = a;
            out[(size_t)(r + 1) * 32 + j] = b;
        }
    }
}

// ---------------- per-feature sum & sumsq over N rows ----------------
__global__ void k_stats(const float* __restrict__ h, double* __restrict__ sums) {
    __shared__ float ssum[32], ssq[32];
    int t = threadIdx.x;
    if (t < 32) { ssum[t] = 0.f; ssq[t] = 0.f; }
    __syncthreads();
    int gid = blockIdx.x * blockDim.x + t;
    int stride = gridDim.x * blockDim.x;     // multiple of 8 -> feature phase constant
    float4 s4 = make_float4(0.f, 0.f, 0.f, 0.f);
    float4 q4 = make_float4(0.f, 0.f, 0.f, 0.f);
    const float4* h4 = (const float4*)h;
    for (size_t i = gid; i < (size_t)N_NODES * 8; i += stride) {
        float4 v = h4[i];
        s4.x += v.x; s4.y += v.y; s4.z += v.z; s4.w += v.w;
        q4.x += v.x * v.x; q4.y += v.y * v.y; q4.z += v.z * v.z; q4.w += v.w * v.w;
    }
    int f0 = (gid & 7) * 4;
    atomicAdd(&ssum[f0 + 0], s4.x); atomicAdd(&ssum[f0 + 1], s4.y);
    atomicAdd(&ssum[f0 + 2], s4.z); atomicAdd(&ssum[f0 + 3], s4.w);
    atomicAdd(&ssq [f0 + 0], q4.x); atomicAdd(&ssq [f0 + 1], q4.y);
    atomicAdd(&ssq [f0 + 2], q4.z); atomicAdd(&ssq [f0 + 3], q4.w);
    __syncthreads();
    if (t < 32) {
        atomicAdd(&sums[t],      (double)ssum[t]);
        atomicAdd(&sums[32 + t], (double)ssq[t]);
    }
}

// ---------------- fold BN into W2/b2 ----------------
__global__ void k_bnfuse(const double* __restrict__ sums,
                         const float* __restrict__ gamma, const float* __restrict__ beta,
                         const float* __restrict__ W2, const float* __restrict__ b2,
                         float* __restrict__ W2eff, float* __restrict__ b2eff) {
    __shared__ float sa[32], sc[32];
    int t = threadIdx.x;  // 32 threads
    double mu  = sums[t] / (double)N_NODES;
    double var = sums[32 + t] / (double)N_NODES - mu * mu;
    float a = gamma[t] / sqrtf((float)var + BN_EPS);
    sa[t] = a;
    sc[t] = beta[t] - (float)mu * a;
    __syncwarp();
    float acc = b2[t];
    for (int k = 0; k < 32; k++) {
        float w = W2[k * 32 + t];
        W2eff[k * 32 + t] = sa[k] * w;
        acc += sc[k] * w;
    }
    b2eff[t] = acc;
}

// ---------------- graph pooling: x_g[b] = sum of 50 consecutive h4 rows ----------------
__global__ void k_pool() {
    int gid = blockIdx.x * blockDim.x + threadIdx.x;
    if (gid >= BATCH * 32) return;
    int b = gid >> 5, f = gid & 31;
    const float* p = g_h2 + (size_t)b * NPG * 32 + f;
    float acc = 0.f;
#pragma unroll 10
    for (int n = 0; n < NPG; n++) acc += p[n * 32];
    g_xg[gid] = acc;
}

// ---------------- decoder weight diff / bias diff / pair index tables ----------------
__global__ void k_initdec(const float* __restrict__ W1d, const float* __restrict__ b1d) {
    int p = blockIdx.x * blockDim.x + threadIdx.x;
    if (p >= NPAIRC) return;
    int i = 0, rem = p;
    while (rem >= NPG - 1 - i) { rem -= NPG - 1 - i; i++; }
    g_iu[p] = i;
    g_ju[p] = i + 1 + rem;
    g_db[p] = b1d[2 * p] - b1d[2 * p + 1];
    for (int k = 0; k < 32; k++)
        g_wT[k * NPAIRC + p] = W1d[k * 2 * NPAIRC + 2 * p] - W1d[k * 2 * NPAIRC + 2 * p + 1];
}

// ---------------- fused decoder GEMM + gumbel hard-argmax -> byte matrix ----------------
__global__ void __launch_bounds__(256) k_decgemm(const float* __restrict__ gn) {
    __shared__ float sd[2048];   // [k][g] 32x64
    __shared__ float sw[2048];   // [k][p] 32x64
    __shared__ float sdb[64];
    __shared__ float sout[4096]; // [g][p] 64x64
    int t = threadIdx.x;
    int g0 = blockIdx.x * 64, p0 = blockIdx.y * 64;
    for (int i = t; i < 2048; i += 256) {
        int k = i >> 6, c = i & 63;
        sd[i] = g_dT[(size_t)k * BATCH + g0 + c];
        int p = p0 + c;
        sw[i] = (p < NPAIRC) ? g_wT[k * NPAIRC + p] : 0.f;
    }
    if (t < 64) sdb[t] = (p0 + t < NPAIRC) ? g_db[p0 + t] : 0.f;
    __syncthreads();
    int gi = (t & 15) * 4, pi = (t >> 4) * 4;
    float acc[4][4];
#pragma unroll
    for (int r = 0; r < 4; r++)
#pragma unroll
        for (int c = 0; c < 4; c++) acc[r][c] = 0.f;
#pragma unroll 8
    for (int k = 0; k < 32; k++) {
        float4 a = *(float4*)&sd[k * 64 + gi];
        float4 w = *(float4*)&sw[k * 64 + pi];
        acc[0][0] += a.x * w.x; acc[0][1] += a.x * w.y; acc[0][2] += a.x * w.z; acc[0][3] += a.x * w.w;
        acc[1][0] += a.y * w.x; acc[1][1] += a.y * w.y; acc[1][2] += a.y * w.z; acc[1][3] += a.y * w.w;
        acc[2][0] += a.z * w.x; acc[2][1] += a.z * w.y; acc[2][2] += a.z * w.z; acc[2][3] += a.z * w.w;
        acc[3][0] += a.w * w.x; acc[3][1] += a.w * w.y; acc[3][2] += a.w * w.z; acc[3][3] += a.w * w.w;
    }
#pragma unroll
    for (int r = 0; r < 4; r++)
        *(float4*)&sout[(gi + r) * 64 + pi] = make_float4(acc[r][0], acc[r][1], acc[r][2], acc[r][3]);
    __syncthreads();
    for (int i = t; i < 4096; i += 256) {
        int g = i >> 6, p = i & 63;
        int pp = p0 + p;
        if (pp < NPAIRC) {
            float2 gv = ((const float2*)gn)[(size_t)(g0 + g) * NPAIRC + pp];
            float m = sout[i] + sdb[p] + gv.x - gv.y;
            g_vals[(size_t)(g0 + g) * NPAIRC + pp] = (m >= 0.f) ? 1 : 0;
        }
    }
}

// ---------------- symmetric adjacency assembly ----------------
__global__ void k_assembly(float* __restrict__ out) {
    __shared__ float tile[2500];
    int t = threadIdx.x;
    int b = blockIdx.x;
    for (int i = t; i < 2500; i += 256) tile[i] = 0.f;
    __syncthreads();
    const unsigned char* vr = g_vals + (size_t)b * NPAIRC;
    for (int p = t; p < NPAIRC; p += 256) {
        float v = vr[p] ? 1.f : 0.f;
        int i = g_iu[p], j = g_ju[p];
        tile[i * NPG + j] = v;
        tile[j * NPG + i] = v;
    }
    __syncthreads();
    float4* o4 = (float4*)(out + (size_t)b * 2500);
    const float4* t4 = (const float4*)tile;
    for (int i = t; i < 625; i += 256) o4[i] = t4[i];
}

// ---------------- host orchestration ----------------
extern "C" void kernel_launch(void* const* d_in, const int* in_sizes, int n_in,
                              void* d_out, int out_size) {
    const float* x    = (const float*)d_in[0];
    const int*   ei   = (const int*)  d_in[1];
    // d_in[2] = batch (implicit: node i -> graph i/50)
    const float* gn   = (const float*)d_in[3];
    const float* e0W1 = (const float*)d_in[4];
    const float* e0b1 = (const float*)d_in[5];
    const float* e0g  = (const float*)d_in[6];
    const float* e0be = (const float*)d_in[7];
    const float* e0W2 = (const float*)d_in[8];
    const float* e0b2 = (const float*)d_in[9];
    const float* e1W1 = (const float*)d_in[10];
    const float* e1b1 = (const float*)d_in[11];
    const float* e1g  = (const float*)d_in[12];
    const float* e1be = (const float*)d_in[13];
    const float* e1W2 = (const float*)d_in[14];
    const float* e1b2 = (const float*)d_in[15];
    const float* dW0  = (const float*)d_in[16];
    const float* db0  = (const float*)d_in[17];
    const float* dW1  = (const float*)d_in[18];
    const float* db1  = (const float*)d_in[19];
    float* out = (float*)d_out;

    void *p_h1, *p_h2, *p_agg32, *p_stats, *p_w2e, *p_b2e, *p_w2e2, *p_b2e2, *p_xg, *p_dT;
    cudaGetSymbolAddress(&p_h1, g_h1);
    cudaGetSymbolAddress(&p_h2, g_h2);
    cudaGetSymbolAddress(&p_agg32, g_agg32);
    cudaGetSymbolAddress(&p_stats, g_stats);
    cudaGetSymbolAddress(&p_w2e, g_W2eff);
    cudaGetSymbolAddress(&p_b2e, g_b2eff);
    cudaGetSymbolAddress(&p_w2e2, g_W2eff2);
    cudaGetSymbolAddress(&p_b2e2, g_b2eff2);
    cudaGetSymbolAddress(&p_xg, g_xg);
    cudaGetSymbolAddress(&p_dT, g_dT);
    float*  f_h1 = (float*)p_h1;
    float*  f_h2 = (float*)p_h2;
    float*  f_agg32 = (float*)p_agg32;
    double* f_stats = (double*)p_stats;

    const int TB = 256;
    // zero scratch + stats
    k_zero<<<35200, TB>>>();
    // pair tables + decoder weight diffs (independent of data flow)
    k_initdec<<<5, TB>>>(dW1, db1);
    // ---- layer 0 ----
    k_scatter0<<<N_EDGES / TB, TB>>>(ei, x);
    k_gin0<<<N_NODES / TB, TB>>>(x, e0W1, e0b1);
    k_stats<<<256, TB>>>(f_h1, f_stats);
    k_bnfuse<<<1, 32>>>(f_stats, e0g, e0be, e0W2, e0b2, (float*)p_w2e, (float*)p_b2e);
    k_linear32<false, false><<<N_NODES / 512, TB>>>(f_h1, nullptr, (float*)p_w2e, (float*)p_b2e,
                                                    f_h2, N_NODES, 0);
    // ---- layer 1 ----
    k_scatter1<<<N_EDGES / TB, TB>>>(ei);
    k_linear32<true, false><<<N_NODES / 512, TB>>>(f_h2, f_agg32, e1W1, e1b1,
                                                   f_h1, N_NODES, 0);
    k_stats<<<256, TB>>>(f_h1, f_stats + 64);
    k_bnfuse<<<1, 32>>>(f_stats + 64, e1g, e1be, e1W2, e1b2, (float*)p_w2e2, (float*)p_b2e2);
    k_linear32<false, false><<<N_NODES / 512, TB>>>(f_h1, nullptr, (float*)p_w2e2, (float*)p_b2e2,
                                                    f_h2, N_NODES, 0);
    // ---- pooling + decoder ----
    k_pool<<<BATCH * 32 / TB, TB>>>();
    k_linear32<false, true><<<BATCH / 512, TB>>>((float*)p_xg, nullptr, dW0, db0,
                                                 (float*)p_dT, BATCH, BATCH);
    dim3 gg(BATCH / 64, (NPAIRC + 63) / 64);
    k_decgemm<<<gg, TB>>>(gn);
    k_assembly<<<BATCH, TB>>>(out);
    (void)in_sizes; (void)n_in; (void)out_size;
}

// round 3
// speedup vs baseline: 1.3429x; 1.3429x over previous
#include <cuda_runtime.h>
#include <math.h>

#define N_NODES 819200
#define N_EDGES 6553600
#define BATCH   16384
#define NPG     50
#define NPAIRC  1225
#define DIN     10
#define BN_EPS  1e-5f

typedef unsigned long long ull;

__device__ __forceinline__ ull pk2(float a, float b) {
    ull r; asm("mov.b64 %0, {%1, %2};" : "=l"(r) : "f"(a), "f"(b)); return r;
}
__device__ __forceinline__ void upk2(ull v, float& a, float& b) {
    asm("mov.b64 {%0, %1}, %2;" : "=f"(a), "=f"(b) : "l"(v));
}
__device__ __forceinline__ ull fma2(ull a, ull b, ull c) {
    ull d; asm("fma.rn.f32x2 %0, %1, %2, %3;" : "=l"(d) : "l"(a), "l"(b), "l"(c)); return d;
}

// ---------------- scratch ----------------
__device__ float g_bufA[(size_t)N_NODES * 32];
__device__ float g_bufB[(size_t)N_NODES * 32];
__device__ int   g_deg[N_NODES];
__device__ int   g_cur[N_NODES];
__device__ int   g_rowptr[N_NODES + 1];
__device__ int   g_csrc[N_EDGES];
__device__ int   g_blksum[1024];
__device__ double g_stats[128];
__device__ float g_W2eff [1024], g_b2eff [32];
__device__ float g_W2eff2[1024], g_b2eff2[32];
__device__ float g_wT[32 * NPAIRC];
__device__ float g_db[NPAIRC];
__device__ int   g_iu[NPAIRC], g_ju[NPAIRC];
__device__ float g_xg[BATCH * 32];
__device__ float g_dT[32 * BATCH];
__device__ unsigned char g_vals[(size_t)BATCH * NPAIRC];

// ---------------- zero scratch ----------------
__global__ void k_zero() {
    size_t i = (size_t)blockIdx.x * blockDim.x + threadIdx.x;
    const size_t nd = N_NODES / 4;          // 204800 int4
    const size_t nx = BATCH * 32 / 4;       // 131072 float4
    if (i < nd)                 ((int4*)g_deg)[i] = make_int4(0, 0, 0, 0);
    else if (i < 2 * nd)        ((int4*)g_cur)[i - nd] = make_int4(0, 0, 0, 0);
    else if (i < 2 * nd + nx)   ((float4*)g_xg)[i - 2 * nd] = make_float4(0.f, 0.f, 0.f, 0.f);
    if (i < 128) g_stats[i] = 0.0;
}

// ---------------- CSR build ----------------
__global__ void k_deg(const int* __restrict__ ei) {
    int e = blockIdx.x * blockDim.x + threadIdx.x;
    if (e >= N_EDGES) return;
    atomicAdd(&g_deg[ei[N_EDGES + e]], 1);
}

__global__ void k_scanA() {
    __shared__ int wsum[32];
    int t = threadIdx.x, b = blockIdx.x;
    int i = b * 1024 + t;
    int v = g_deg[i];
    int lane = t & 31, wid = t >> 5;
    int x = v;
#pragma unroll
    for (int o = 1; o < 32; o <<= 1) {
        int y = __shfl_up_sync(0xffffffffu, x, o);
        if (lane >= o) x += y;
    }
    if (lane == 31) wsum[wid] = x;
    __syncthreads();
    if (wid == 0) {
        int w = wsum[lane];
#pragma unroll
        for (int o = 1; o < 32; o <<= 1) {
            int y = __shfl_up_sync(0xffffffffu, w, o);
            if (lane >= o) w += y;
        }
        wsum[lane] = w;
    }
    __syncthreads();
    int excl = x - v + (wid > 0 ? wsum[wid - 1] : 0);
    g_rowptr[i] = excl;
    if (t == 1023) g_blksum[b] = excl + v;
}

__global__ void k_scanB() {
    __shared__ int wsum[32];
    int t = threadIdx.x;
    int v = (t < 800) ? g_blksum[t] : 0;
    int lane = t & 31, wid = t >> 5;
    int x = v;
#pragma unroll
    for (int o = 1; o < 32; o <<= 1) {
        int y = __shfl_up_sync(0xffffffffu, x, o);
        if (lane >= o) x += y;
    }
    if (lane == 31) wsum[wid] = x;
    __syncthreads();
    if (wid == 0) {
        int w = wsum[lane];
#pragma unroll
        for (int o = 1; o < 32; o <<= 1) {
            int y = __shfl_up_sync(0xffffffffu, w, o);
            if (lane >= o) w += y;
        }
        wsum[lane] = w;
    }
    __syncthreads();
    int excl = x - v + (wid > 0 ? wsum[wid - 1] : 0);
    if (t < 800) g_blksum[t] = excl;
}

__global__ void k_scanC() {
    int i = blockIdx.x * 1024 + threadIdx.x;
    g_rowptr[i] += g_blksum[blockIdx.x];
    if (i == 0) g_rowptr[N_NODES] = N_EDGES;
}

__global__ void k_fill(const int* __restrict__ ei) {
    int e = blockIdx.x * blockDim.x + threadIdx.x;
    if (e >= N_EDGES) return;
    int s = ei[e];
    int t = ei[N_EDGES + e];
    int pos = atomicAdd(&g_cur[t], 1);
    g_csrc[g_rowptr[t] + pos] = s;
}

// ---------------- z0 = x @ W1 (no bias) ----------------
__global__ void __launch_bounds__(256) k_z0(const float* __restrict__ x,
                                            const float* __restrict__ W1,
                                            float* __restrict__ out) {
    __shared__ float sW[DIN * 32];
    int t = threadIdx.x;
    for (int i = t; i < DIN * 32; i += 256) sW[i] = W1[i];
    __syncthreads();
    int n = blockIdx.x * 256 + t;
    const float2* xr = (const float2*)(x + (size_t)n * DIN);
    float2 x0 = xr[0], x1 = xr[1], x2 = xr[2], x3 = xr[3], x4 = xr[4];
    float s[DIN] = {x0.x, x0.y, x1.x, x1.y, x2.x, x2.y, x3.x, x3.y, x4.x, x4.y};
    float* o = out + (size_t)n * 32;
#pragma unroll 4
    for (int j = 0; j < 32; j += 4) {
        float4 r;
        float a0 = 0.f, a1 = 0.f, a2 = 0.f, a3 = 0.f;
#pragma unroll
        for (int k = 0; k < DIN; k++) {
            float sv = s[k];
            a0 += sv * sW[k * 32 + j];
            a1 += sv * sW[k * 32 + j + 1];
            a2 += sv * sW[k * 32 + j + 2];
            a3 += sv * sW[k * 32 + j + 3];
        }
        r.x = a0; r.y = a1; r.z = a2; r.w = a3;
        *(float4*)(o + j) = r;
    }
}

// ---------------- gather: out = relu(z[self] + sum_nbr z[nbr] + b) ----------------
__global__ void __launch_bounds__(256) k_gather(const float* __restrict__ z,
                                                const float* __restrict__ bias,
                                                float* __restrict__ out) {
    int w = blockIdx.x * 8 + (threadIdx.x >> 5);
    int t = threadIdx.x & 31;
    int beg = g_rowptr[w], end = g_rowptr[w + 1];
    float acc0 = z[(size_t)w * 32 + t];
    float acc1 = 0.f;
    int e = beg;
    for (; e + 8 <= end; e += 8) {
        int s0 = __ldg(&g_csrc[e]);
        int s1 = __ldg(&g_csrc[e + 1]);
        int s2 = __ldg(&g_csrc[e + 2]);
        int s3 = __ldg(&g_csrc[e + 3]);
        int s4 = __ldg(&g_csrc[e + 4]);
        int s5 = __ldg(&g_csrc[e + 5]);
        int s6 = __ldg(&g_csrc[e + 6]);
        int s7 = __ldg(&g_csrc[e + 7]);
        float v0 = z[(size_t)s0 * 32 + t];
        float v1 = z[(size_t)s1 * 32 + t];
        float v2 = z[(size_t)s2 * 32 + t];
        float v3 = z[(size_t)s3 * 32 + t];
        float v4 = z[(size_t)s4 * 32 + t];
        float v5 = z[(size_t)s5 * 32 + t];
        float v6 = z[(size_t)s6 * 32 + t];
        float v7 = z[(size_t)s7 * 32 + t];
        acc0 += v0 + v2 + v4 + v6;
        acc1 += v1 + v3 + v5 + v7;
    }
    for (; e < end; e++) acc0 += z[(size_t)__ldg(&g_csrc[e]) * 32 + t];
    out[(size_t)w * 32 + t] = fmaxf(acc0 + acc1 + bias[t], 0.f);
}

// ---------------- fused dual 32x32 matmul: z2 = relu(h@W2eff+b2eff) @ W1 ----------------
__global__ void __launch_bounds__(256) k_mid(const float* __restrict__ in,
                                             const float* __restrict__ W2eff,
                                             const float* __restrict__ b2eff,
                                             const float* __restrict__ W1n,
                                             float* __restrict__ out) {
    __shared__ float2 sWa[1024];
    __shared__ float2 sWb[1024];
    __shared__ ull sB[32];
    int t = threadIdx.x;
    for (int i = t; i < 1024; i += 256) {
        float w = W2eff[i]; sWa[i] = make_float2(w, w);
        float v = W1n[i];   sWb[i] = make_float2(v, v);
    }
    if (t < 32) { float b = b2eff[t]; sB[t] = pk2(b, b); }
    __syncthreads();
    size_t r = ((size_t)blockIdx.x * 256 + t) * 2;
    ull h[32];
    {
        const float4* ra = (const float4*)(in + r * 32);
        const float4* rb = (const float4*)(in + r * 32 + 32);
#pragma unroll
        for (int q = 0; q < 8; q++) {
            float4 a = ra[q], b = rb[q];
            h[4*q+0] = pk2(a.x, b.x); h[4*q+1] = pk2(a.y, b.y);
            h[4*q+2] = pk2(a.z, b.z); h[4*q+3] = pk2(a.w, b.w);
        }
    }
    ull m[32];
    const ulonglong2* Wa = (const ulonglong2*)sWa;
    const ulonglong2* Wb = (const ulonglong2*)sWb;
#pragma unroll
    for (int jg = 0; jg < 4; jg++) {
        ull a0 = sB[jg*8+0], a1 = sB[jg*8+1], a2 = sB[jg*8+2], a3 = sB[jg*8+3];
        ull a4 = sB[jg*8+4], a5 = sB[jg*8+5], a6 = sB[jg*8+6], a7 = sB[jg*8+7];
#pragma unroll
        for (int k = 0; k < 32; k++) {
            int base = k * 16 + jg * 4;
            ulonglong2 w01 = Wa[base], w23 = Wa[base+1], w45 = Wa[base+2], w67 = Wa[base+3];
            a0 = fma2(h[k], w01.x, a0); a1 = fma2(h[k], w01.y, a1);
            a2 = fma2(h[k], w23.x, a2); a3 = fma2(h[k], w23.y, a3);
            a4 = fma2(h[k], w45.x, a4); a5 = fma2(h[k], w45.y, a5);
            a6 = fma2(h[k], w67.x, a6); a7 = fma2(h[k], w67.y, a7);
        }
        float lo, hi;
        upk2(a0, lo, hi); m[jg*8+0] = pk2(fmaxf(lo, 0.f), fmaxf(hi, 0.f));
        upk2(a1, lo, hi); m[jg*8+1] = pk2(fmaxf(lo, 0.f), fmaxf(hi, 0.f));
        upk2(a2, lo, hi); m[jg*8+2] = pk2(fmaxf(lo, 0.f), fmaxf(hi, 0.f));
        upk2(a3, lo, hi); m[jg*8+3] = pk2(fmaxf(lo, 0.f), fmaxf(hi, 0.f));
        upk2(a4, lo, hi); m[jg*8+4] = pk2(fmaxf(lo, 0.f), fmaxf(hi, 0.f));
        upk2(a5, lo, hi); m[jg*8+5] = pk2(fmaxf(lo, 0.f), fmaxf(hi, 0.f));
        upk2(a6, lo, hi); m[jg*8+6] = pk2(fmaxf(lo, 0.f), fmaxf(hi, 0.f));
        upk2(a7, lo, hi); m[jg*8+7] = pk2(fmaxf(lo, 0.f), fmaxf(hi, 0.f));
    }
#pragma unroll
    for (int jg = 0; jg < 4; jg++) {
        ull a0 = 0, a1 = 0, a2 = 0, a3 = 0, a4 = 0, a5 = 0, a6 = 0, a7 = 0;
#pragma unroll
        for (int k = 0; k < 32; k++) {
            int base = k * 16 + jg * 4;
            ulonglong2 w01 = Wb[base], w23 = Wb[base+1], w45 = Wb[base+2], w67 = Wb[base+3];
            a0 = fma2(m[k], w01.x, a0); a1 = fma2(m[k], w01.y, a1);
            a2 = fma2(m[k], w23.x, a2); a3 = fma2(m[k], w23.y, a3);
            a4 = fma2(m[k], w45.x, a4); a5 = fma2(m[k], w45.y, a5);
            a6 = fma2(m[k], w67.x, a6); a7 = fma2(m[k], w67.y, a7);
        }
        float A0,A1,A2,A3,A4,A5,A6,A7,B0,B1,B2,B3,B4,B5,B6,B7;
        upk2(a0, A0, B0); upk2(a1, A1, B1); upk2(a2, A2, B2); upk2(a3, A3, B3);
        upk2(a4, A4, B4); upk2(a5, A5, B5); upk2(a6, A6, B6); upk2(a7, A7, B7);
        float4* oa = (float4*)(out + r * 32 + jg * 8);
        float4* ob = (float4*)(out + r * 32 + 32 + jg * 8);
        oa[0] = make_float4(A0, A1, A2, A3); oa[1] = make_float4(A4, A5, A6, A7);
        ob[0] = make_float4(B0, B1, B2, B3); ob[1] = make_float4(B4, B5, B6, B7);
    }
}

// ---------------- single 32x32 matmul + relu (f32x2) ----------------
__global__ void __launch_bounds__(256) k_lin1(const float* __restrict__ in,
                                              const float* __restrict__ W,
                                              const float* __restrict__ bias,
                                              float* __restrict__ out) {
    __shared__ float2 sW[1024];
    __shared__ ull sB[32];
    int t = threadIdx.x;
    for (int i = t; i < 1024; i += 256) { float w = W[i]; sW[i] = make_float2(w, w); }
    if (t < 32) { float b = bias[t]; sB[t] = pk2(b, b); }
    __syncthreads();
    size_t r = ((size_t)blockIdx.x * 256 + t) * 2;
    ull h[32];
    {
        const float4* ra = (const float4*)(in + r * 32);
        const float4* rb = (const float4*)(in + r * 32 + 32);
#pragma unroll
        for (int q = 0; q < 8; q++) {
            float4 a = ra[q], b = rb[q];
            h[4*q+0] = pk2(a.x, b.x); h[4*q+1] = pk2(a.y, b.y);
            h[4*q+2] = pk2(a.z, b.z); h[4*q+3] = pk2(a.w, b.w);
        }
    }
    const ulonglong2* Wv = (const ulonglong2*)sW;
#pragma unroll
    for (int jg = 0; jg < 4; jg++) {
        ull a0 = sB[jg*8+0], a1 = sB[jg*8+1], a2 = sB[jg*8+2], a3 = sB[jg*8+3];
        ull a4 = sB[jg*8+4], a5 = sB[jg*8+5], a6 = sB[jg*8+6], a7 = sB[jg*8+7];
#pragma unroll
        for (int k = 0; k < 32; k++) {
            int base = k * 16 + jg * 4;
            ulonglong2 w01 = Wv[base], w23 = Wv[base+1], w45 = Wv[base+2], w67 = Wv[base+3];
            a0 = fma2(h[k], w01.x, a0); a1 = fma2(h[k], w01.y, a1);
            a2 = fma2(h[k], w23.x, a2); a3 = fma2(h[k], w23.y, a3);
            a4 = fma2(h[k], w45.x, a4); a5 = fma2(h[k], w45.y, a5);
            a6 = fma2(h[k], w67.x, a6); a7 = fma2(h[k], w67.y, a7);
        }
        float A0,A1,A2,A3,A4,A5,A6,A7,B0,B1,B2,B3,B4,B5,B6,B7;
        upk2(a0, A0, B0); upk2(a1, A1, B1); upk2(a2, A2, B2); upk2(a3, A3, B3);
        upk2(a4, A4, B4); upk2(a5, A5, B5); upk2(a6, A6, B6); upk2(a7, A7, B7);
        float4* oa = (float4*)(out + r * 32 + jg * 8);
        float4* ob = (float4*)(out + r * 32 + 32 + jg * 8);
        oa[0] = make_float4(fmaxf(A0,0.f), fmaxf(A1,0.f), fmaxf(A2,0.f), fmaxf(A3,0.f));
        oa[1] = make_float4(fmaxf(A4,0.f), fmaxf(A5,0.f), fmaxf(A6,0.f), fmaxf(A7,0.f));
        ob[0] = make_float4(fmaxf(B0,0.f), fmaxf(B1,0.f), fmaxf(B2,0.f), fmaxf(B3,0.f));
        ob[1] = make_float4(fmaxf(B4,0.f), fmaxf(B5,0.f), fmaxf(B6,0.f), fmaxf(B7,0.f));
    }
}

// ---------------- stats ----------------
__global__ void k_stats(const float* __restrict__ h, double* __restrict__ sums) {
    __shared__ float ssum[32], ssq[32];
    int t = threadIdx.x;
    if (t < 32) { ssum[t] = 0.f; ssq[t] = 0.f; }
    __syncthreads();
    int gid = blockIdx.x * blockDim.x + t;
    int stride = gridDim.x * blockDim.x;
    float4 s4 = make_float4(0.f, 0.f, 0.f, 0.f);
    float4 q4 = make_float4(0.f, 0.f, 0.f, 0.f);
    const float4* h4 = (const float4*)h;
    for (size_t i = gid; i < (size_t)N_NODES * 8; i += stride) {
        float4 v = h4[i];
        s4.x += v.x; s4.y += v.y; s4.z += v.z; s4.w += v.w;
        q4.x += v.x * v.x; q4.y += v.y * v.y; q4.z += v.z * v.z; q4.w += v.w * v.w;
    }
    int f0 = (gid & 7) * 4;
    atomicAdd(&ssum[f0 + 0], s4.x); atomicAdd(&ssum[f0 + 1], s4.y);
    atomicAdd(&ssum[f0 + 2], s4.z); atomicAdd(&ssum[f0 + 3], s4.w);
    atomicAdd(&ssq [f0 + 0], q4.x); atomicAdd(&ssq [f0 + 1], q4.y);
    atomicAdd(&ssq [f0 + 2], q4.z); atomicAdd(&ssq [f0 + 3], q4.w);
    __syncthreads();
    if (t < 32) {
        atomicAdd(&sums[t],      (double)ssum[t]);
        atomicAdd(&sums[32 + t], (double)ssq[t]);
    }
}

// ---------------- fold BN into W2/b2 ----------------
__global__ void k_bnfuse(const double* __restrict__ sums,
                         const float* __restrict__ gamma, const float* __restrict__ beta,
                         const float* __restrict__ W2, const float* __restrict__ b2,
                         float* __restrict__ W2eff, float* __restrict__ b2eff) {
    __shared__ float sa[32], sc[32];
    int t = threadIdx.x;
    double mu  = sums[t] / (double)N_NODES;
    double var = sums[32 + t] / (double)N_NODES - mu * mu;
    float a = gamma[t] / sqrtf((float)var + BN_EPS);
    sa[t] = a;
    sc[t] = beta[t] - (float)mu * a;
    __syncwarp();
    float acc = b2[t];
    for (int k = 0; k < 32; k++) {
        float w = W2[k * 32 + t];
        W2eff[k * 32 + t] = sa[k] * w;
        acc += sc[k] * w;
    }
    b2eff[t] = acc;
}

// ---------------- pooling ----------------
__global__ void k_pool(const float* __restrict__ h4) {
    int gid = blockIdx.x * blockDim.x + threadIdx.x;
    if (gid >= BATCH * 32) return;
    int b = gid >> 5, f = gid & 31;
    const float* p = h4 + (size_t)b * NPG * 32 + f;
    float acc = 0.f;
#pragma unroll 10
    for (int n = 0; n < NPG; n++) acc += p[n * 32];
    g_xg[gid] = acc;
}

// ---------------- decoder first layer (transposed output) ----------------
__global__ void __launch_bounds__(256) k_declin(
    const float* __restrict__ in, const float* __restrict__ W,
    const float* __restrict__ bias, float* __restrict__ out) {
    __shared__ float sW[1024];
    __shared__ float sb[32];
    int t = threadIdx.x;
    for (int i = t; i < 1024; i += 256) sW[i] = W[i];
    if (t < 32) sb[t] = bias[t];
    __syncthreads();
    int r = (blockIdx.x * 256 + t) * 2;
    if (r >= BATCH) return;
    float hA[32], hB[32];
    const float4* ia = (const float4*)(in + (size_t)r * 32);
    const float4* ib = (const float4*)(in + (size_t)(r + 1) * 32);
#pragma unroll
    for (int q = 0; q < 8; q++) {
        float4 v = ia[q];
        hA[4*q] = v.x; hA[4*q+1] = v.y; hA[4*q+2] = v.z; hA[4*q+3] = v.w;
        float4 w = ib[q];
        hB[4*q] = w.x; hB[4*q+1] = w.y; hB[4*q+2] = w.z; hB[4*q+3] = w.w;
    }
#pragma unroll 2
    for (int j = 0; j < 32; j++) {
        float a = sb[j], b = sb[j];
#pragma unroll
        for (int k = 0; k < 32; k++) {
            float w = sW[k * 32 + j];
            a += hA[k] * w;
            b += hB[k] * w;
        }
        out[(size_t)j * BATCH + r]     = fmaxf(a, 0.f);
        out[(size_t)j * BATCH + r + 1] = fmaxf(b, 0.f);
    }
}

// ---------------- decoder weight/bias diff + pair tables ----------------
__global__ void k_initdec(const float* __restrict__ W1d, const float* __restrict__ b1d) {
    int p = blockIdx.x * blockDim.x + threadIdx.x;
    if (p >= NPAIRC) return;
    int i = 0, rem = p;
    while (rem >= NPG - 1 - i) { rem -= NPG - 1 - i; i++; }
    g_iu[p] = i;
    g_ju[p] = i + 1 + rem;
    g_db[p] = b1d[2 * p] - b1d[2 * p + 1];
    for (int k = 0; k < 32; k++)
        g_wT[k * NPAIRC + p] = W1d[k * 2 * NPAIRC + 2 * p] - W1d[k * 2 * NPAIRC + 2 * p + 1];
}

// ---------------- fused decoder GEMM + gumbel hard-argmax ----------------
__global__ void __launch_bounds__(256) k_decgemm(const float* __restrict__ gn) {
    __shared__ float sd[2048];
    __shared__ float sw[2048];
    __shared__ float sdb[64];
    __shared__ float sout[4096];
    int t = threadIdx.x;
    int g0 = blockIdx.x * 64, p0 = blockIdx.y * 64;
    for (int i = t; i < 2048; i += 256) {
        int k = i >> 6, c = i & 63;
        sd[i] = g_dT[(size_t)k * BATCH + g0 + c];
        int p = p0 + c;
        sw[i] = (p < NPAIRC) ? g_wT[k * NPAIRC + p] : 0.f;
    }
    if (t < 64) sdb[t] = (p0 + t < NPAIRC) ? g_db[p0 + t] : 0.f;
    __syncthreads();
    int gi = (t & 15) * 4, pi = (t >> 4) * 4;
    float acc[4][4];
#pragma unroll
    for (int r = 0; r < 4; r++)
#pragma unroll
        for (int c = 0; c < 4; c++) acc[r][c] = 0.f;
#pragma unroll 8
    for (int k = 0; k < 32; k++) {
        float4 a = *(float4*)&sd[k * 64 + gi];
        float4 w = *(float4*)&sw[k * 64 + pi];
        acc[0][0] += a.x * w.x; acc[0][1] += a.x * w.y; acc[0][2] += a.x * w.z; acc[0][3] += a.x * w.w;
        acc[1][0] += a.y * w.x; acc[1][1] += a.y * w.y; acc[1][2] += a.y * w.z; acc[1][3] += a.y * w.w;
        acc[2][0] += a.z * w.x; acc[2][1] += a.z * w.y; acc[2][2] += a.z * w.z; acc[2][3] += a.z * w.w;
        acc[3][0] += a.w * w.x; acc[3][1] += a.w * w.y; acc[3][2] += a.w * w.z; acc[3][3] += a.w * w.w;
    }
#pragma unroll
    for (int r = 0; r < 4; r++)
        *(float4*)&sout[(gi + r) * 64 + pi] = make_float4(acc[r][0], acc[r][1], acc[r][2], acc[r][3]);
    __syncthreads();
    for (int i = t; i < 4096; i += 256) {
        int g = i >> 6, p = i & 63;
        int pp = p0 + p;
        if (pp < NPAIRC) {
            float2 gv = ((const float2*)gn)[(size_t)(g0 + g) * NPAIRC + pp];
            float m = sout[i] + sdb[p] + gv.x - gv.y;
            g_vals[(size_t)(g0 + g) * NPAIRC + pp] = (m >= 0.f) ? 1 : 0;
        }
    }
}

// ---------------- symmetric adjacency assembly ----------------
__global__ void k_assembly(float* __restrict__ out) {
    __shared__ float tile[2500];
    int t = threadIdx.x;
    int b = blockIdx.x;
    for (int i = t; i < 2500; i += 256) tile[i] = 0.f;
    __syncthreads();
    const unsigned char* vr = g_vals + (size_t)b * NPAIRC;
    for (int p = t; p < NPAIRC; p += 256) {
        float v = vr[p] ? 1.f : 0.f;
        int i = g_iu[p], j = g_ju[p];
        tile[i * NPG + j] = v;
        tile[j * NPG + i] = v;
    }
    __syncthreads();
    float4* o4 = (float4*)(out + (size_t)b * 2500);
    const float4* t4 = (const float4*)tile;
    for (int i = t; i < 625; i += 256) o4[i] = t4[i];
}

// ---------------- host orchestration ----------------
extern "C" void kernel_launch(void* const* d_in, const int* in_sizes, int n_in,
                              void* d_out, int out_size) {
    const float* x    = (const float*)d_in[0];
    const int*   ei   = (const int*)  d_in[1];
    const float* gn   = (const float*)d_in[3];
    const float* e0W1 = (const float*)d_in[4];
    const float* e0b1 = (const float*)d_in[5];
    const float* e0g  = (const float*)d_in[6];
    const float* e0be = (const float*)d_in[7];
    const float* e0W2 = (const float*)d_in[8];
    const float* e0b2 = (const float*)d_in[9];
    const float* e1W1 = (const float*)d_in[10];
    const float* e1b1 = (const float*)d_in[11];
    const float* e1g  = (const float*)d_in[12];
    const float* e1be = (const float*)d_in[13];
    const float* e1W2 = (const float*)d_in[14];
    const float* e1b2 = (const float*)d_in[15];
    const float* dW0  = (const float*)d_in[16];
    const float* db0  = (const float*)d_in[17];
    const float* dW1  = (const float*)d_in[18];
    const float* db1  = (const float*)d_in[19];
    float* out = (float*)d_out;

    void *p_bufA, *p_bufB, *p_stats, *p_w2e, *p_b2e, *p_w2e2, *p_b2e2, *p_xg, *p_dT;
    cudaGetSymbolAddress(&p_bufA, g_bufA);
    cudaGetSymbolAddress(&p_bufB, g_bufB);
    cudaGetSymbolAddress(&p_stats, g_stats);
    cudaGetSymbolAddress(&p_w2e, g_W2eff);
    cudaGetSymbolAddress(&p_b2e, g_b2eff);
    cudaGetSymbolAddress(&p_w2e2, g_W2eff2);
    cudaGetSymbolAddress(&p_b2e2, g_b2eff2);
    cudaGetSymbolAddress(&p_xg, g_xg);
    cudaGetSymbolAddress(&p_dT, g_dT);
    float*  bufA = (float*)p_bufA;
    float*  bufB = (float*)p_bufB;
    double* stats = (double*)p_stats;

    const int TB = 256;
    k_zero<<<2112, TB>>>();
    k_initdec<<<5, TB>>>(dW1, db1);
    // CSR build
    k_deg<<<N_EDGES / TB, TB>>>(ei);
    k_scanA<<<800, 1024>>>();
    k_scanB<<<1, 1024>>>();
    k_scanC<<<800, 1024>>>();
    k_fill<<<N_EDGES / TB, TB>>>(ei);
    // layer 0
    k_z0<<<N_NODES / TB, TB>>>(x, e0W1, bufA);
    k_gather<<<N_NODES / 8, TB>>>(bufA, e0b1, bufB);            // h1
    k_stats<<<512, TB>>>(bufB, stats);
    k_bnfuse<<<1, 32>>>(stats, e0g, e0be, e0W2, e0b2, (float*)p_w2e, (float*)p_b2e);
    // fused: h2 = relu(h1@W2eff+b2eff); z2 = h2@e1W1
    k_mid<<<N_NODES / 512, TB>>>(bufB, (float*)p_w2e, (float*)p_b2e, e1W1, bufA);
    // layer 1
    k_gather<<<N_NODES / 8, TB>>>(bufA, e1b1, bufB);            // h3
    k_stats<<<512, TB>>>(bufB, stats + 64);
    k_bnfuse<<<1, 32>>>(stats + 64, e1g, e1be, e1W2, e1b2, (float*)p_w2e2, (float*)p_b2e2);
    k_lin1<<<N_NODES / 512, TB>>>(bufB, (float*)p_w2e2, (float*)p_b2e2, bufA);  // h4
    // pooling + decoder
    k_pool<<<BATCH * 32 / TB, TB>>>(bufA);
    k_declin<<<BATCH / 512, TB>>>((float*)p_xg, dW0, db0, (float*)p_dT);
    dim3 gg(BATCH / 64, (NPAIRC + 63) / 64);
    k_decgemm<<<gg, TB>>>(gn);
    k_assembly<<<BATCH, TB>>>(out);
    (void)in_sizes; (void)n_in; (void)out_size;
}

// round 4
// speedup vs baseline: 1.5301x; 1.1394x over previous
#include <cuda_runtime.h>
#include <math.h>

#define N_NODES 819200
#define N_EDGES 6553600
#define BATCH   16384
#define NPG     50
#define NPAIRC  1225
#define DIN     10
#define BN_EPS  1e-5f

typedef unsigned long long ull;

__device__ __forceinline__ ull pk2(float a, float b) {
    ull r; asm("mov.b64 %0, {%1, %2};" : "=l"(r) : "f"(a), "f"(b)); return r;
}
__device__ __forceinline__ void upk2(ull v, float& a, float& b) {
    asm("mov.b64 {%0, %1}, %2;" : "=f"(a), "=f"(b) : "l"(v));
}
__device__ __forceinline__ ull fma2(ull a, ull b, ull c) {
    ull d; asm("fma.rn.f32x2 %0, %1, %2, %3;" : "=l"(d) : "l"(a), "l"(b), "l"(c)); return d;
}
__device__ __forceinline__ ull mk_evict_last_policy() {
    ull pol; asm("createpolicy.fractional.L2::evict_last.b64 %0, 1.0;" : "=l"(pol));
    return pol;
}
__device__ __forceinline__ float ld_el(const float* p, ull pol) {
    float v; asm volatile("ld.global.L2::cache_hint.f32 %0, [%1], %2;"
                          : "=f"(v) : "l"(p), "l"(pol)); return v;
}

// ---------------- scratch ----------------
__device__ float g_bufA[(size_t)N_NODES * 32];
__device__ float g_bufB[(size_t)N_NODES * 32];
__device__ int   g_deg[N_NODES];
__device__ int   g_rowptr[N_NODES + 1];
__device__ int   g_csrc[N_EDGES];
__device__ int   g_blksum[1024];
__device__ float g_part0[2048];            // 32 slots x (32 sum + 32 sq)
__device__ float g_part1[2048];
__device__ float g_W2eff [1024], g_b2eff [32];
__device__ float g_W2eff2[1024], g_b2eff2[32];
__device__ float g_wT[32 * NPAIRC];
__device__ float g_db[NPAIRC];
__device__ int   g_iu[NPAIRC], g_ju[NPAIRC];
__device__ float g_xg[BATCH * 32];
__device__ float g_dT[32 * BATCH];
__device__ unsigned char g_vals[(size_t)BATCH * NPAIRC];

// ---------------- zero scratch ----------------
__global__ void k_zero() {
    size_t i = (size_t)blockIdx.x * blockDim.x + threadIdx.x;
    const size_t nd = N_NODES / 4;          // 204800 int4
    if (i < nd) ((int4*)g_deg)[i] = make_int4(0, 0, 0, 0);
    if (i < 2048) { g_part0[i] = 0.f; g_part1[i] = 0.f; }
}

// ---------------- CSR build ----------------
__global__ void k_deg(const int* __restrict__ ei) {
    int i = blockIdx.x * blockDim.x + threadIdx.x;   // N_EDGES/4 threads
    int4 t4 = ((const int4*)(ei + N_EDGES))[i];
    atomicAdd(&g_deg[t4.x], 1);
    atomicAdd(&g_deg[t4.y], 1);
    atomicAdd(&g_deg[t4.z], 1);
    atomicAdd(&g_deg[t4.w], 1);
}

__global__ void k_scanA() {
    __shared__ int wsum[32];
    int t = threadIdx.x, b = blockIdx.x;
    int i = b * 1024 + t;
    int v = g_deg[i];
    int lane = t & 31, wid = t >> 5;
    int x = v;
#pragma unroll
    for (int o = 1; o < 32; o <<= 1) {
        int y = __shfl_up_sync(0xffffffffu, x, o);
        if (lane >= o) x += y;
    }
    if (lane == 31) wsum[wid] = x;
    __syncthreads();
    if (wid == 0) {
        int w = wsum[lane];
#pragma unroll
        for (int o = 1; o < 32; o <<= 1) {
            int y = __shfl_up_sync(0xffffffffu, w, o);
            if (lane >= o) w += y;
        }
        wsum[lane] = w;
    }
    __syncthreads();
    int excl = x - v + (wid > 0 ? wsum[wid - 1] : 0);
    g_rowptr[i] = excl;
    if (t == 1023) g_blksum[b] = excl + v;
}

__global__ void k_scanB() {
    __shared__ int wsum[32];
    int t = threadIdx.x;
    int v = (t < 800) ? g_blksum[t] : 0;
    int lane = t & 31, wid = t >> 5;
    int x = v;
#pragma unroll
    for (int o = 1; o < 32; o <<= 1) {
        int y = __shfl_up_sync(0xffffffffu, x, o);
        if (lane >= o) x += y;
    }
    if (lane == 31) wsum[wid] = x;
    __syncthreads();
    if (wid == 0) {
        int w = wsum[lane];
#pragma unroll
        for (int o = 1; o < 32; o <<= 1) {
            int y = __shfl_up_sync(0xffffffffu, w, o);
            if (lane >= o) w += y;
        }
        wsum[lane] = w;
    }
    __syncthreads();
    int excl = x - v + (wid > 0 ? wsum[wid - 1] : 0);
    if (t < 800) g_blksum[t] = excl;
}

__global__ void k_scanC() {
    int i = blockIdx.x * 1024 + threadIdx.x;
    g_rowptr[i] += g_blksum[blockIdx.x];
}

// fill with cursor-on-rowptr: after this, rowptr[i] = prefix[i+1]
__global__ void k_fill(const int* __restrict__ ei) {
    int e2 = (blockIdx.x * blockDim.x + threadIdx.x) * 2;
    int2 s = *(const int2*)(ei + e2);
    int2 tg = *(const int2*)(ei + N_EDGES + e2);
    int p0 = atomicAdd(&g_rowptr[tg.x], 1);
    g_csrc[p0] = s.x;
    int p1 = atomicAdd(&g_rowptr[tg.y], 1);
    g_csrc[p1] = s.y;
}

// ---------------- z0 = x @ W1 (no bias) ----------------
__global__ void __launch_bounds__(256) k_z0(const float* __restrict__ x,
                                            const float* __restrict__ W1,
                                            float* __restrict__ out) {
    __shared__ float sW[DIN * 32];
    int t = threadIdx.x;
    for (int i = t; i < DIN * 32; i += 256) sW[i] = W1[i];
    __syncthreads();
    int n = blockIdx.x * 256 + t;
    const float2* xr = (const float2*)(x + (size_t)n * DIN);
    float2 x0 = xr[0], x1 = xr[1], x2 = xr[2], x3 = xr[3], x4 = xr[4];
    float s[DIN] = {x0.x, x0.y, x1.x, x1.y, x2.x, x2.y, x3.x, x3.y, x4.x, x4.y};
    float* o = out + (size_t)n * 32;
#pragma unroll 4
    for (int j = 0; j < 32; j += 4) {
        float a0 = 0.f, a1 = 0.f, a2 = 0.f, a3 = 0.f;
#pragma unroll
        for (int k = 0; k < DIN; k++) {
            float sv = s[k];
            a0 += sv * sW[k * 32 + j];
            a1 += sv * sW[k * 32 + j + 1];
            a2 += sv * sW[k * 32 + j + 2];
            a3 += sv * sW[k * 32 + j + 3];
        }
        *(float4*)(o + j) = make_float4(a0, a1, a2, a3);
    }
}

// ---------------- gather + fused BN stats ----------------
// warp w handles 8 nodes; z rows loaded with L2 evict_last; h written streaming.
__global__ void __launch_bounds__(256) k_gather(const float* __restrict__ z,
                                                const float* __restrict__ bias,
                                                float* __restrict__ out,
                                                float* __restrict__ part) {
    __shared__ float sred[2][8][32];
    __shared__ float sb[32];
    int t = threadIdx.x, w = t >> 5, lane = t & 31;
    if (t < 32) sb[t] = bias[t];
    __syncthreads();
    ull pol = mk_evict_last_policy();
    float ls = 0.f, lq = 0.f;
    int nbase = blockIdx.x * 64 + w * 8;
#pragma unroll 1
    for (int i = 0; i < 8; i++) {
        int n = nbase + i;
        int beg = (n == 0) ? 0 : __ldg(&g_rowptr[n - 1]);
        int end = __ldg(&g_rowptr[n]);
        float acc0 = ld_el(z + (size_t)n * 32 + lane, pol) + sb[lane];
        float acc1 = 0.f;
        int e = beg;
        for (; e + 8 <= end; e += 8) {
            int s0 = __ldcs(&g_csrc[e]);
            int s1 = __ldcs(&g_csrc[e + 1]);
            int s2 = __ldcs(&g_csrc[e + 2]);
            int s3 = __ldcs(&g_csrc[e + 3]);
            int s4 = __ldcs(&g_csrc[e + 4]);
            int s5 = __ldcs(&g_csrc[e + 5]);
            int s6 = __ldcs(&g_csrc[e + 6]);
            int s7 = __ldcs(&g_csrc[e + 7]);
            float v0 = ld_el(z + (size_t)s0 * 32 + lane, pol);
            float v1 = ld_el(z + (size_t)s1 * 32 + lane, pol);
            float v2 = ld_el(z + (size_t)s2 * 32 + lane, pol);
            float v3 = ld_el(z + (size_t)s3 * 32 + lane, pol);
            float v4 = ld_el(z + (size_t)s4 * 32 + lane, pol);
            float v5 = ld_el(z + (size_t)s5 * 32 + lane, pol);
            float v6 = ld_el(z + (size_t)s6 * 32 + lane, pol);
            float v7 = ld_el(z + (size_t)s7 * 32 + lane, pol);
            acc0 += v0 + v2 + v4 + v6;
            acc1 += v1 + v3 + v5 + v7;
        }
        for (; e < end; e++)
            acc0 += ld_el(z + (size_t)__ldcs(&g_csrc[e]) * 32 + lane, pol);
        float v = fmaxf(acc0 + acc1, 0.f);
        __stcs(out + (size_t)n * 32 + lane, v);
        ls += v; lq += v * v;
    }
    sred[0][w][lane] = ls;
    sred[1][w][lane] = lq;
    __syncthreads();
    if (t < 64) {
        int which = t >> 5;
        float s = 0.f;
#pragma unroll
        for (int i = 0; i < 8; i++) s += sred[which][i][lane];
        atomicAdd(&part[(blockIdx.x & 31) * 64 + which * 32 + lane], s);
    }
}

// ---------------- fold BN into W2/b2 (reads float partials) ----------------
__global__ void k_bnfuse(const float* __restrict__ part,
                         const float* __restrict__ gamma, const float* __restrict__ beta,
                         const float* __restrict__ W2, const float* __restrict__ b2,
                         float* __restrict__ W2eff, float* __restrict__ b2eff) {
    __shared__ float sa[32], sc[32];
    int t = threadIdx.x;
    double s = 0.0, q = 0.0;
    for (int sl = 0; sl < 32; sl++) {
        s += (double)part[sl * 64 + t];
        q += (double)part[sl * 64 + 32 + t];
    }
    double mu  = s / (double)N_NODES;
    double var = q / (double)N_NODES - mu * mu;
    float a = gamma[t] / sqrtf((float)var + BN_EPS);
    sa[t] = a;
    sc[t] = beta[t] - (float)mu * a;
    __syncwarp();
    float acc = b2[t];
    for (int k = 0; k < 32; k++) {
        float w = W2[k * 32 + t];
        W2eff[k * 32 + t] = sa[k] * w;
        acc += sc[k] * w;
    }
    b2eff[t] = acc;
}

// ---------------- fused dual 32x32 matmul: z2 = relu(h@W2eff+b2eff) @ W1 ----------------
__global__ void __launch_bounds__(256) k_mid(const float* __restrict__ in,
                                             const float* __restrict__ W2eff,
                                             const float* __restrict__ b2eff,
                                             const float* __restrict__ W1n,
                                             float* __restrict__ out) {
    __shared__ float2 sWa[1024];
    __shared__ float2 sWb[1024];
    __shared__ ull sB[32];
    int t = threadIdx.x;
    for (int i = t; i < 1024; i += 256) {
        float w = W2eff[i]; sWa[i] = make_float2(w, w);
        float v = W1n[i];   sWb[i] = make_float2(v, v);
    }
    if (t < 32) { float b = b2eff[t]; sB[t] = pk2(b, b); }
    __syncthreads();
    size_t r = ((size_t)blockIdx.x * 256 + t) * 2;
    ull h[32];
    {
        const float4* ra = (const float4*)(in + r * 32);
        const float4* rb = (const float4*)(in + r * 32 + 32);
#pragma unroll
        for (int q = 0; q < 8; q++) {
            float4 a = __ldcs(ra + q), b = __ldcs(rb + q);
            h[4*q+0] = pk2(a.x, b.x); h[4*q+1] = pk2(a.y, b.y);
            h[4*q+2] = pk2(a.z, b.z); h[4*q+3] = pk2(a.w, b.w);
        }
    }
    ull m[32];
    const ulonglong2* Wa = (const ulonglong2*)sWa;
    const ulonglong2* Wb = (const ulonglong2*)sWb;
#pragma unroll
    for (int jg = 0; jg < 4; jg++) {
        ull a0 = sB[jg*8+0], a1 = sB[jg*8+1], a2 = sB[jg*8+2], a3 = sB[jg*8+3];
        ull a4 = sB[jg*8+4], a5 = sB[jg*8+5], a6 = sB[jg*8+6], a7 = sB[jg*8+7];
#pragma unroll
        for (int k = 0; k < 32; k++) {
            int base = k * 16 + jg * 4;
            ulonglong2 w01 = Wa[base], w23 = Wa[base+1], w45 = Wa[base+2], w67 = Wa[base+3];
            a0 = fma2(h[k], w01.x, a0); a1 = fma2(h[k], w01.y, a1);
            a2 = fma2(h[k], w23.x, a2); a3 = fma2(h[k], w23.y, a3);
            a4 = fma2(h[k], w45.x, a4); a5 = fma2(h[k], w45.y, a5);
            a6 = fma2(h[k], w67.x, a6); a7 = fma2(h[k], w67.y, a7);
        }
        float lo, hi;
        upk2(a0, lo, hi); m[jg*8+0] = pk2(fmaxf(lo, 0.f), fmaxf(hi, 0.f));
        upk2(a1, lo, hi); m[jg*8+1] = pk2(fmaxf(lo, 0.f), fmaxf(hi, 0.f));
        upk2(a2, lo, hi); m[jg*8+2] = pk2(fmaxf(lo, 0.f), fmaxf(hi, 0.f));
        upk2(a3, lo, hi); m[jg*8+3] = pk2(fmaxf(lo, 0.f), fmaxf(hi, 0.f));
        upk2(a4, lo, hi); m[jg*8+4] = pk2(fmaxf(lo, 0.f), fmaxf(hi, 0.f));
        upk2(a5, lo, hi); m[jg*8+5] = pk2(fmaxf(lo, 0.f), fmaxf(hi, 0.f));
        upk2(a6, lo, hi); m[jg*8+6] = pk2(fmaxf(lo, 0.f), fmaxf(hi, 0.f));
        upk2(a7, lo, hi); m[jg*8+7] = pk2(fmaxf(lo, 0.f), fmaxf(hi, 0.f));
    }
#pragma unroll
    for (int jg = 0; jg < 4; jg++) {
        ull a0 = 0, a1 = 0, a2 = 0, a3 = 0, a4 = 0, a5 = 0, a6 = 0, a7 = 0;
#pragma unroll
        for (int k = 0; k < 32; k++) {
            int base = k * 16 + jg * 4;
            ulonglong2 w01 = Wb[base], w23 = Wb[base+1], w45 = Wb[base+2], w67 = Wb[base+3];
            a0 = fma2(m[k], w01.x, a0); a1 = fma2(m[k], w01.y, a1);
            a2 = fma2(m[k], w23.x, a2); a3 = fma2(m[k], w23.y, a3);
            a4 = fma2(m[k], w45.x, a4); a5 = fma2(m[k], w45.y, a5);
            a6 = fma2(m[k], w67.x, a6); a7 = fma2(m[k], w67.y, a7);
        }
        float A0,A1,A2,A3,A4,A5,A6,A7,B0,B1,B2,B3,B4,B5,B6,B7;
        upk2(a0, A0, B0); upk2(a1, A1, B1); upk2(a2, A2, B2); upk2(a3, A3, B3);
        upk2(a4, A4, B4); upk2(a5, A5, B5); upk2(a6, A6, B6); upk2(a7, A7, B7);
        float4* oa = (float4*)(out + r * 32 + jg * 8);
        float4* ob = (float4*)(out + r * 32 + 32 + jg * 8);
        oa[0] = make_float4(A0, A1, A2, A3); oa[1] = make_float4(A4, A5, A6, A7);
        ob[0] = make_float4(B0, B1, B2, B3); ob[1] = make_float4(B4, B5, B6, B7);
    }
}

// ---------------- fused final layer + graph pooling ----------------
// block = 400 threads = 800 rows = 16 graphs. xg[g*32+j] = sum_rows relu(h@W+b)
__global__ void __launch_bounds__(400) k_linpool(const float* __restrict__ in,
                                                 const float* __restrict__ W,
                                                 const float* __restrict__ bias,
                                                 float* __restrict__ xg) {
    __shared__ float2 sW[1024];
    __shared__ ull sB[32];
    __shared__ float sbuf[32 * 401];
    int t = threadIdx.x;
    for (int i = t; i < 1024; i += 400) { float w = W[i]; sW[i] = make_float2(w, w); }
    if (t < 32) { float b = bias[t]; sB[t] = pk2(b, b); }
    __syncthreads();
    size_t r = ((size_t)blockIdx.x * 400 + t) * 2;
    ull h[32];
    {
        const float4* ra = (const float4*)(in + r * 32);
        const float4* rb = (const float4*)(in + r * 32 + 32);
#pragma unroll
        for (int q = 0; q < 8; q++) {
            float4 a = __ldcs(ra + q), b = __ldcs(rb + q);
            h[4*q+0] = pk2(a.x, b.x); h[4*q+1] = pk2(a.y, b.y);
            h[4*q+2] = pk2(a.z, b.z); h[4*q+3] = pk2(a.w, b.w);
        }
    }
    const ulonglong2* Wv = (const ulonglong2*)sW;
#pragma unroll
    for (int jg = 0; jg < 4; jg++) {
        ull a0 = sB[jg*8+0], a1 = sB[jg*8+1], a2 = sB[jg*8+2], a3 = sB[jg*8+3];
        ull a4 = sB[jg*8+4], a5 = sB[jg*8+5], a6 = sB[jg*8+6], a7 = sB[jg*8+7];
#pragma unroll
        for (int k = 0; k < 32; k++) {
            int base = k * 16 + jg * 4;
            ulonglong2 w01 = Wv[base], w23 = Wv[base+1], w45 = Wv[base+2], w67 = Wv[base+3];
            a0 = fma2(h[k], w01.x, a0); a1 = fma2(h[k], w01.y, a1);
            a2 = fma2(h[k], w23.x, a2); a3 = fma2(h[k], w23.y, a3);
            a4 = fma2(h[k], w45.x, a4); a5 = fma2(h[k], w45.y, a5);
            a6 = fma2(h[k], w67.x, a6); a7 = fma2(h[k], w67.y, a7);
        }
        float lo, hi;
        // relu each row value, then sum the pair (both rows in same graph: 50 is even)
        upk2(a0, lo, hi); sbuf[(jg*8+0)*401 + t] = fmaxf(lo,0.f) + fmaxf(hi,0.f);
        upk2(a1, lo, hi); sbuf[(jg*8+1)*401 + t] = fmaxf(lo,0.f) + fmaxf(hi,0.f);
        upk2(a2, lo, hi); sbuf[(jg*8+2)*401 + t] = fmaxf(lo,0.f) + fmaxf(hi,0.f);
        upk2(a3, lo, hi); sbuf[(jg*8+3)*401 + t] = fmaxf(lo,0.f) + fmaxf(hi,0.f);
        upk2(a4, lo, hi); sbuf[(jg*8+4)*401 + t] = fmaxf(lo,0.f) + fmaxf(hi,0.f);
        upk2(a5, lo, hi); sbuf[(jg*8+5)*401 + t] = fmaxf(lo,0.f) + fmaxf(hi,0.f);
        upk2(a6, lo, hi); sbuf[(jg*8+6)*401 + t] = fmaxf(lo,0.f) + fmaxf(hi,0.f);
        upk2(a7, lo, hi); sbuf[(jg*8+7)*401 + t] = fmaxf(lo,0.f) + fmaxf(hi,0.f);
    }
    __syncthreads();
    for (int o = t; o < 512; o += 400) {
        int g = o >> 5, j = o & 31;
        const float* p = &sbuf[j * 401 + g * 25];
        float s = 0.f;
#pragma unroll
        for (int q = 0; q < 25; q++) s += p[q];
        xg[(size_t)blockIdx.x * 512 + o] = s;
    }
}

// ---------------- decoder first layer (transposed output) ----------------
__global__ void __launch_bounds__(256) k_declin(
    const float* __restrict__ in, const float* __restrict__ W,
    const float* __restrict__ bias, float* __restrict__ out) {
    __shared__ float sW[1024];
    __shared__ float sb[32];
    int t = threadIdx.x;
    for (int i = t; i < 1024; i += 256) sW[i] = W[i];
    if (t < 32) sb[t] = bias[t];
    __syncthreads();
    int r = (blockIdx.x * 256 + t) * 2;
    if (r >= BATCH) return;
    float hA[32], hB[32];
    const float4* ia = (const float4*)(in + (size_t)r * 32);
    const float4* ib = (const float4*)(in + (size_t)(r + 1) * 32);
#pragma unroll
    for (int q = 0; q < 8; q++) {
        float4 v = ia[q];
        hA[4*q] = v.x; hA[4*q+1] = v.y; hA[4*q+2] = v.z; hA[4*q+3] = v.w;
        float4 w = ib[q];
        hB[4*q] = w.x; hB[4*q+1] = w.y; hB[4*q+2] = w.z; hB[4*q+3] = w.w;
    }
#pragma unroll 2
    for (int j = 0; j < 32; j++) {
        float a = sb[j], b = sb[j];
#pragma unroll
        for (int k = 0; k < 32; k++) {
            float w = sW[k * 32 + j];
            a += hA[k] * w;
            b += hB[k] * w;
        }
        out[(size_t)j * BATCH + r]     = fmaxf(a, 0.f);
        out[(size_t)j * BATCH + r + 1] = fmaxf(b, 0.f);
    }
}

// ---------------- decoder weight/bias diff + pair tables (parallel over k,p) ----------------
__global__ void k_initdec(const float* __restrict__ W1d, const float* __restrict__ b1d) {
    int idx = blockIdx.x * blockDim.x + threadIdx.x;
    if (idx >= 32 * NPAIRC) return;
    int k = idx / NPAIRC, p = idx - k * NPAIRC;
    g_wT[idx] = W1d[k * 2 * NPAIRC + 2 * p] - W1d[k * 2 * NPAIRC + 2 * p + 1];
    if (k == 0) {
        int i = 0, rem = p;
        while (rem >= NPG - 1 - i) { rem -= NPG - 1 - i; i++; }
        g_iu[p] = i;
        g_ju[p] = i + 1 + rem;
        g_db[p] = b1d[2 * p] - b1d[2 * p + 1];
    }
}

// ---------------- fused decoder GEMM + gumbel hard-argmax ----------------
__global__ void __launch_bounds__(256) k_decgemm(const float* __restrict__ gn) {
    __shared__ float sd[2048];
    __shared__ float sw[2048];
    __shared__ float sdb[64];
    __shared__ float sout[4096];
    int t = threadIdx.x;
    int g0 = blockIdx.x * 64, p0 = blockIdx.y * 64;
    for (int i = t; i < 2048; i += 256) {
        int k = i >> 6, c = i & 63;
        sd[i] = g_dT[(size_t)k * BATCH + g0 + c];
        int p = p0 + c;
        sw[i] = (p < NPAIRC) ? g_wT[k * NPAIRC + p] : 0.f;
    }
    if (t < 64) sdb[t] = (p0 + t < NPAIRC) ? g_db[p0 + t] : 0.f;
    __syncthreads();
    int gi = (t & 15) * 4, pi = (t >> 4) * 4;
    float acc[4][4];
#pragma unroll
    for (int r = 0; r < 4; r++)
#pragma unroll
        for (int c = 0; c < 4; c++) acc[r][c] = 0.f;
#pragma unroll 8
    for (int k = 0; k < 32; k++) {
        float4 a = *(float4*)&sd[k * 64 + gi];
        float4 w = *(float4*)&sw[k * 64 + pi];
        acc[0][0] += a.x * w.x; acc[0][1] += a.x * w.y; acc[0][2] += a.x * w.z; acc[0][3] += a.x * w.w;
        acc[1][0] += a.y * w.x; acc[1][1] += a.y * w.y; acc[1][2] += a.y * w.z; acc[1][3] += a.y * w.w;
        acc[2][0] += a.z * w.x; acc[2][1] += a.z * w.y; acc[2][2] += a.z * w.z; acc[2][3] += a.z * w.w;
        acc[3][0] += a.w * w.x; acc[3][1] += a.w * w.y; acc[3][2] += a.w * w.z; acc[3][3] += a.w * w.w;
    }
#pragma unroll
    for (int r = 0; r < 4; r++)
        *(float4*)&sout[(gi + r) * 64 + pi] = make_float4(acc[r][0], acc[r][1], acc[r][2], acc[r][3]);
    __syncthreads();
    for (int i = t; i < 4096; i += 256) {
        int g = i >> 6, p = i & 63;
        int pp = p0 + p;
        if (pp < NPAIRC) {
            float2 gv = __ldcs((const float2*)gn + (size_t)(g0 + g) * NPAIRC + pp);
            float m = sout[i] + sdb[p] + gv.x - gv.y;
            g_vals[(size_t)(g0 + g) * NPAIRC + pp] = (m >= 0.f) ? 1 : 0;
        }
    }
}

// ---------------- symmetric adjacency assembly ----------------
__global__ void k_assembly(float* __restrict__ out) {
    __shared__ float tile[2500];
    int t = threadIdx.x;
    int b = blockIdx.x;
    for (int i = t; i < 2500; i += 256) tile[i] = 0.f;
    __syncthreads();
    const unsigned char* vr = g_vals + (size_t)b * NPAIRC;
    for (int p = t; p < NPAIRC; p += 256) {
        float v = vr[p] ? 1.f : 0.f;
        int i = g_iu[p], j = g_ju[p];
        tile[i * NPG + j] = v;
        tile[j * NPG + i] = v;
    }
    __syncthreads();
    float4* o4 = (float4*)(out + (size_t)b * 2500);
    const float4* t4 = (const float4*)tile;
    for (int i = t; i < 625; i += 256) {
        float4 v = t4[i];
        __stcs(o4 + i, v);
    }
}

// ---------------- host orchestration ----------------
extern "C" void kernel_launch(void* const* d_in, const int* in_sizes, int n_in,
                              void* d_out, int out_size) {
    const float* x    = (const float*)d_in[0];
    const int*   ei   = (const int*)  d_in[1];
    const float* gn   = (const float*)d_in[3];
    const float* e0W1 = (const float*)d_in[4];
    const float* e0b1 = (const float*)d_in[5];
    const float* e0g  = (const float*)d_in[6];
    const float* e0be = (const float*)d_in[7];
    const float* e0W2 = (const float*)d_in[8];
    const float* e0b2 = (const float*)d_in[9];
    const float* e1W1 = (const float*)d_in[10];
    const float* e1b1 = (const float*)d_in[11];
    const float* e1g  = (const float*)d_in[12];
    const float* e1be = (const float*)d_in[13];
    const float* e1W2 = (const float*)d_in[14];
    const float* e1b2 = (const float*)d_in[15];
    const float* dW0  = (const float*)d_in[16];
    const float* db0  = (const float*)d_in[17];
    const float* dW1  = (const float*)d_in[18];
    const float* db1  = (const float*)d_in[19];
    float* out = (float*)d_out;

    void *p_bufA, *p_bufB, *p_part0, *p_part1, *p_w2e, *p_b2e, *p_w2e2, *p_b2e2, *p_xg, *p_dT;
    cudaGetSymbolAddress(&p_bufA, g_bufA);
    cudaGetSymbolAddress(&p_bufB, g_bufB);
    cudaGetSymbolAddress(&p_part0, g_part0);
    cudaGetSymbolAddress(&p_part1, g_part1);
    cudaGetSymbolAddress(&p_w2e, g_W2eff);
    cudaGetSymbolAddress(&p_b2e, g_b2eff);
    cudaGetSymbolAddress(&p_w2e2, g_W2eff2);
    cudaGetSymbolAddress(&p_b2e2, g_b2eff2);
    cudaGetSymbolAddress(&p_xg, g_xg);
    cudaGetSymbolAddress(&p_dT, g_dT);
    float* bufA = (float*)p_bufA;
    float* bufB = (float*)p_bufB;

    const int TB = 256;

    // fork a second captured stream for work independent of the CSR build
    cudaStream_t s2;
    cudaStreamCreateWithFlags(&s2, cudaStreamNonBlocking);
    cudaEvent_t eF, eJ;
    cudaEventCreateWithFlags(&eF, cudaEventDisableTiming);
    cudaEventCreateWithFlags(&eJ, cudaEventDisableTiming);
    cudaEventRecord(eF, 0);
    cudaStreamWaitEvent(s2, eF, 0);
    k_initdec<<<(32 * NPAIRC + TB - 1) / TB, TB, 0, s2>>>(dW1, db1);
    k_z0<<<N_NODES / TB, TB, 0, s2>>>(x, e0W1, bufA);
    cudaEventRecord(eJ, s2);

    // main stream: zero + CSR build
    k_zero<<<801, TB>>>();
    k_deg<<<N_EDGES / 4 / TB, TB>>>(ei);
    k_scanA<<<800, 1024>>>();
    k_scanB<<<1, 1024>>>();
    k_scanC<<<800, 1024>>>();
    k_fill<<<N_EDGES / 2 / TB, TB>>>(ei);
    cudaStreamWaitEvent(0, eJ, 0);

    // layer 0
    k_gather<<<N_NODES / 64, TB>>>(bufA, e0b1, bufB, (float*)p_part0);
    k_bnfuse<<<1, 32>>>((float*)p_part0, e0g, e0be, e0W2, e0b2, (float*)p_w2e, (float*)p_b2e);
    k_mid<<<N_NODES / 512, TB>>>(bufB, (float*)p_w2e, (float*)p_b2e, e1W1, bufA);
    // layer 1
    k_gather<<<N_NODES / 64, TB>>>(bufA, e1b1, bufB, (float*)p_part1);
    k_bnfuse<<<1, 32>>>((float*)p_part1, e1g, e1be, e1W2, e1b2, (float*)p_w2e2, (float*)p_b2e2);
    k_linpool<<<N_NODES / 800, 400>>>(bufB, (float*)p_w2e2, (float*)p_b2e2, (float*)p_xg);
    // decoder
    k_declin<<<BATCH / 512, TB>>>((float*)p_xg, dW0, db0, (float*)p_dT);
    dim3 gg(BATCH / 64, (NPAIRC + 63) / 64);
    k_decgemm<<<gg, TB>>>(gn);
    k_assembly<<<BATCH, TB>>>(out);
    (void)in_sizes; (void)n_in; (void)out_size;
}

// round 6
// speedup vs baseline: 1.5614x; 1.0205x over previous
#include <cuda_runtime.h>
#include <math.h>

#define N_NODES 819200
#define N_EDGES 6553600
#define BATCH   16384
#define NPG     50
#define NPAIRC  1225
#define DIN     10
#define BN_EPS  1e-5f

typedef unsigned long long ull;

__device__ __forceinline__ ull pk2(float a, float b) {
    ull r; asm("mov.b64 %0, {%1, %2};" : "=l"(r) : "f"(a), "f"(b)); return r;
}
__device__ __forceinline__ void upk2(ull v, float& a, float& b) {
    asm("mov.b64 {%0, %1}, %2;" : "=f"(a), "=f"(b) : "l"(v));
}
__device__ __forceinline__ ull fma2(ull a, ull b, ull c) {
    ull d; asm("fma.rn.f32x2 %0, %1, %2, %3;" : "=l"(d) : "l"(a), "l"(b), "l"(c)); return d;
}
__device__ __forceinline__ ull mk_evict_last_policy() {
    ull pol; asm("createpolicy.fractional.L2::evict_last.b64 %0, 1.0;" : "=l"(pol));
    return pol;
}
__device__ __forceinline__ float ld_el(const float* p, ull pol) {
    float v; asm volatile("ld.global.L2::cache_hint.f32 %0, [%1], %2;"
                          : "=f"(v) : "l"(p), "l"(pol)); return v;
}

// ---------------- scratch ----------------
__device__ float g_bufA[(size_t)N_NODES * 32];
__device__ float g_bufB[(size_t)N_NODES * 32];
__device__ int   g_deg[N_NODES];
__device__ int   g_rowptr[N_NODES + 1];
__device__ int   g_csrc[N_EDGES];
__device__ int   g_blksum[1024];
__device__ float g_part0[2048];            // 32 slots x (32 sum + 32 sq)
__device__ float g_part1[2048];
__device__ float g_W2eff [1024], g_b2eff [32];
__device__ float g_W2eff2[1024], g_b2eff2[32];
__device__ float g_wT[32 * NPAIRC];
__device__ float g_db[NPAIRC];
__device__ int   g_iu[NPAIRC], g_ju[NPAIRC];
__device__ float g_xg[BATCH * 32];
__device__ float g_dT[32 * BATCH];
__device__ unsigned char g_vals[(size_t)BATCH * NPAIRC];

// ---------------- zero scratch ----------------
__global__ void k_zero() {
    size_t i = (size_t)blockIdx.x * blockDim.x + threadIdx.x;
    const size_t nd = N_NODES / 4;          // 204800 int4
    if (i < nd) ((int4*)g_deg)[i] = make_int4(0, 0, 0, 0);
    if (i < 2048) { g_part0[i] = 0.f; g_part1[i] = 0.f; }
}

// ---------------- CSR build ----------------
__global__ void k_deg(const int* __restrict__ ei) {
    int i = blockIdx.x * blockDim.x + threadIdx.x;   // N_EDGES/4 threads
    int4 t4 = ((const int4*)(ei + N_EDGES))[i];
    atomicAdd(&g_deg[t4.x], 1);
    atomicAdd(&g_deg[t4.y], 1);
    atomicAdd(&g_deg[t4.z], 1);
    atomicAdd(&g_deg[t4.w], 1);
}

__global__ void k_scanA() {
    __shared__ int wsum[32];
    int t = threadIdx.x, b = blockIdx.x;
    int i = b * 1024 + t;
    int v = g_deg[i];
    int lane = t & 31, wid = t >> 5;
    int x = v;
#pragma unroll
    for (int o = 1; o < 32; o <<= 1) {
        int y = __shfl_up_sync(0xffffffffu, x, o);
        if (lane >= o) x += y;
    }
    if (lane == 31) wsum[wid] = x;
    __syncthreads();
    if (wid == 0) {
        int w = wsum[lane];
#pragma unroll
        for (int o = 1; o < 32; o <<= 1) {
            int y = __shfl_up_sync(0xffffffffu, w, o);
            if (lane >= o) w += y;
        }
        wsum[lane] = w;
    }
    __syncthreads();
    int excl = x - v + (wid > 0 ? wsum[wid - 1] : 0);
    g_rowptr[i] = excl;
    if (t == 1023) g_blksum[b] = excl + v;
}

__global__ void k_scanB() {
    __shared__ int wsum[32];
    int t = threadIdx.x;
    int v = (t < 800) ? g_blksum[t] : 0;
    int lane = t & 31, wid = t >> 5;
    int x = v;
#pragma unroll
    for (int o = 1; o < 32; o <<= 1) {
        int y = __shfl_up_sync(0xffffffffu, x, o);
        if (lane >= o) x += y;
    }
    if (lane == 31) wsum[wid] = x;
    __syncthreads();
    if (wid == 0) {
        int w = wsum[lane];
#pragma unroll
        for (int o = 1; o < 32; o <<= 1) {
            int y = __shfl_up_sync(0xffffffffu, w, o);
            if (lane >= o) w += y;
        }
        wsum[lane] = w;
    }
    __syncthreads();
    int excl = x - v + (wid > 0 ? wsum[wid - 1] : 0);
    if (t < 800) g_blksum[t] = excl;
}

__global__ void k_scanC() {
    int i = blockIdx.x * 1024 + threadIdx.x;
    g_rowptr[i] += g_blksum[blockIdx.x];
}

// fill with cursor-on-rowptr: after this, rowptr[i] = prefix[i+1]
__global__ void k_fill(const int* __restrict__ ei) {
    int i = blockIdx.x * blockDim.x + threadIdx.x;   // N_EDGES/4 threads
    int4 s  = ((const int4*)ei)[i];
    int4 tg = ((const int4*)(ei + N_EDGES))[i];
    int p0 = atomicAdd(&g_rowptr[tg.x], 1);
    int p1 = atomicAdd(&g_rowptr[tg.y], 1);
    int p2 = atomicAdd(&g_rowptr[tg.z], 1);
    int p3 = atomicAdd(&g_rowptr[tg.w], 1);
    g_csrc[p0] = s.x;
    g_csrc[p1] = s.y;
    g_csrc[p2] = s.z;
    g_csrc[p3] = s.w;
}

// ---------------- z0 = x @ W1 (no bias) ----------------
__global__ void __launch_bounds__(256) k_z0(const float* __restrict__ x,
                                            const float* __restrict__ W1,
                                            float* __restrict__ out) {
    __shared__ float sW[DIN * 32];
    int t = threadIdx.x;
    for (int i = t; i < DIN * 32; i += 256) sW[i] = W1[i];
    __syncthreads();
    int n = blockIdx.x * 256 + t;
    const float2* xr = (const float2*)(x + (size_t)n * DIN);
    float2 x0 = xr[0], x1 = xr[1], x2 = xr[2], x3 = xr[3], x4 = xr[4];
    float s[DIN] = {x0.x, x0.y, x1.x, x1.y, x2.x, x2.y, x3.x, x3.y, x4.x, x4.y};
    float* o = out + (size_t)n * 32;
#pragma unroll 4
    for (int j = 0; j < 32; j += 4) {
        float a0 = 0.f, a1 = 0.f, a2 = 0.f, a3 = 0.f;
#pragma unroll
        for (int k = 0; k < DIN; k++) {
            float sv = s[k];
            a0 += sv * sW[k * 32 + j];
            a1 += sv * sW[k * 32 + j + 1];
            a2 += sv * sW[k * 32 + j + 2];
            a3 += sv * sW[k * 32 + j + 3];
        }
        *(float4*)(o + j) = make_float4(a0, a1, a2, a3);
    }
}

// ---------------- gather + fused BN stats ----------------
// warp w handles 8 nodes. Predicated 8-wide edge batches: full MLP even on
// partial batches (no serial remainder loop).
__global__ void __launch_bounds__(256) k_gather(const float* __restrict__ z,
                                                const float* __restrict__ bias,
                                                float* __restrict__ out,
                                                float* __restrict__ part) {
    __shared__ float sred[2][8][32];
    __shared__ float sb[32];
    int t = threadIdx.x, w = t >> 5, lane = t & 31;
    if (t < 32) sb[t] = bias[t];
    __syncthreads();
    ull pol = mk_evict_last_policy();
    float ls = 0.f, lq = 0.f;
    int nbase = blockIdx.x * 64 + w * 8;
    // lane-parallel fetch of the 9 rowptr values this warp needs
    int rp = 0;
    if (lane < 9) {
        int idx = nbase - 1 + lane;
        rp = (idx < 0) ? 0 : __ldg(&g_rowptr[idx]);
    }
#pragma unroll 1
    for (int i = 0; i < 8; i++) {
        int n = nbase + i;
        int beg = __shfl_sync(0xffffffffu, rp, i);
        int end = __shfl_sync(0xffffffffu, rp, i + 1);
        float acc0 = ld_el(z + (size_t)n * 32 + lane, pol) + sb[lane];
        float acc1 = 0.f;
#pragma unroll 1
        for (int e = beg; e < end; e += 8) {
            int rem = end - e;
            float v0 = 0.f, v1 = 0.f, v2 = 0.f, v3 = 0.f;
            float v4 = 0.f, v5 = 0.f, v6 = 0.f, v7 = 0.f;
            if (rem > 0) v0 = ld_el(z + (size_t)__ldcs(&g_csrc[e    ]) * 32 + lane, pol);
            if (rem > 1) v1 = ld_el(z + (size_t)__ldcs(&g_csrc[e + 1]) * 32 + lane, pol);
            if (rem > 2) v2 = ld_el(z + (size_t)__ldcs(&g_csrc[e + 2]) * 32 + lane, pol);
            if (rem > 3) v3 = ld_el(z + (size_t)__ldcs(&g_csrc[e + 3]) * 32 + lane, pol);
            if (rem > 4) v4 = ld_el(z + (size_t)__ldcs(&g_csrc[e + 4]) * 32 + lane, pol);
            if (rem > 5) v5 = ld_el(z + (size_t)__ldcs(&g_csrc[e + 5]) * 32 + lane, pol);
            if (rem > 6) v6 = ld_el(z + (size_t)__ldcs(&g_csrc[e + 6]) * 32 + lane, pol);
            if (rem > 7) v7 = ld_el(z + (size_t)__ldcs(&g_csrc[e + 7]) * 32 + lane, pol);
            acc0 += (v0 + v2) + (v4 + v6);
            acc1 += (v1 + v3) + (v5 + v7);
        }
        float v = fmaxf(acc0 + acc1, 0.f);
        __stcs(out + (size_t)n * 32 + lane, v);
        ls += v; lq += v * v;
    }
    sred[0][w][lane] = ls;
    sred[1][w][lane] = lq;
    __syncthreads();
    if (t < 64) {
        int which = t >> 5;
        float s = 0.f;
#pragma unroll
        for (int i = 0; i < 8; i++) s += sred[which][i][lane];
        atomicAdd(&part[(blockIdx.x & 31) * 64 + which * 32 + lane], s);
    }
}

// ---------------- fold BN into W2/b2 (reads float partials) ----------------
__global__ void k_bnfuse(const float* __restrict__ part,
                         const float* __restrict__ gamma, const float* __restrict__ beta,
                         const float* __restrict__ W2, const float* __restrict__ b2,
                         float* __restrict__ W2eff, float* __restrict__ b2eff) {
    __shared__ float sa[32], sc[32];
    int t = threadIdx.x;
    double s = 0.0, q = 0.0;
    for (int sl = 0; sl < 32; sl++) {
        s += (double)part[sl * 64 + t];
        q += (double)part[sl * 64 + 32 + t];
    }
    double mu  = s / (double)N_NODES;
    double var = q / (double)N_NODES - mu * mu;
    float a = gamma[t] / sqrtf((float)var + BN_EPS);
    sa[t] = a;
    sc[t] = beta[t] - (float)mu * a;
    __syncwarp();
    float acc = b2[t];
    for (int k = 0; k < 32; k++) {
        float w = W2[k * 32 + t];
        W2eff[k * 32 + t] = sa[k] * w;
        acc += sc[k] * w;
    }
    b2eff[t] = acc;
}

// ---------------- fused dual 32x32 matmul: z2 = relu(h@W2eff+b2eff) @ W1 ----------------
__global__ void __launch_bounds__(256) k_mid(const float* __restrict__ in,
                                             const float* __restrict__ W2eff,
                                             const float* __restrict__ b2eff,
                                             const float* __restrict__ W1n,
                                             float* __restrict__ out) {
    __shared__ float2 sWa[1024];
    __shared__ float2 sWb[1024];
    __shared__ ull sB[32];
    int t = threadIdx.x;
    for (int i = t; i < 1024; i += 256) {
        float w = W2eff[i]; sWa[i] = make_float2(w, w);
        float v = W1n[i];   sWb[i] = make_float2(v, v);
    }
    if (t < 32) { float b = b2eff[t]; sB[t] = pk2(b, b); }
    __syncthreads();
    size_t r = ((size_t)blockIdx.x * 256 + t) * 2;
    ull h[32];
    {
        const float4* ra = (const float4*)(in + r * 32);
        const float4* rb = (const float4*)(in + r * 32 + 32);
#pragma unroll
        for (int q = 0; q < 8; q++) {
            float4 a = __ldcs(ra + q), b = __ldcs(rb + q);
            h[4*q+0] = pk2(a.x, b.x); h[4*q+1] = pk2(a.y, b.y);
            h[4*q+2] = pk2(a.z, b.z); h[4*q+3] = pk2(a.w, b.w);
        }
    }
    ull m[32];
    const ulonglong2* Wa = (const ulonglong2*)sWa;
    const ulonglong2* Wb = (const ulonglong2*)sWb;
#pragma unroll
    for (int jg = 0; jg < 4; jg++) {
        ull a0 = sB[jg*8+0], a1 = sB[jg*8+1], a2 = sB[jg*8+2], a3 = sB[jg*8+3];
        ull a4 = sB[jg*8+4], a5 = sB[jg*8+5], a6 = sB[jg*8+6], a7 = sB[jg*8+7];
#pragma unroll
        for (int k = 0; k < 32; k++) {
            int base = k * 16 + jg * 4;
            ulonglong2 w01 = Wa[base], w23 = Wa[base+1], w45 = Wa[base+2], w67 = Wa[base+3];
            a0 = fma2(h[k], w01.x, a0); a1 = fma2(h[k], w01.y, a1);
            a2 = fma2(h[k], w23.x, a2); a3 = fma2(h[k], w23.y, a3);
            a4 = fma2(h[k], w45.x, a4); a5 = fma2(h[k], w45.y, a5);
            a6 = fma2(h[k], w67.x, a6); a7 = fma2(h[k], w67.y, a7);
        }
        float lo, hi;
        upk2(a0, lo, hi); m[jg*8+0] = pk2(fmaxf(lo, 0.f), fmaxf(hi, 0.f));
        upk2(a1, lo, hi); m[jg*8+1] = pk2(fmaxf(lo, 0.f), fmaxf(hi, 0.f));
        upk2(a2, lo, hi); m[jg*8+2] = pk2(fmaxf(lo, 0.f), fmaxf(hi, 0.f));
        upk2(a3, lo, hi); m[jg*8+3] = pk2(fmaxf(lo, 0.f), fmaxf(hi, 0.f));
        upk2(a4, lo, hi); m[jg*8+4] = pk2(fmaxf(lo, 0.f), fmaxf(hi, 0.f));
        upk2(a5, lo, hi); m[jg*8+5] = pk2(fmaxf(lo, 0.f), fmaxf(hi, 0.f));
        upk2(a6, lo, hi); m[jg*8+6] = pk2(fmaxf(lo, 0.f), fmaxf(hi, 0.f));
        upk2(a7, lo, hi); m[jg*8+7] = pk2(fmaxf(lo, 0.f), fmaxf(hi, 0.f));
    }
#pragma unroll
    for (int jg = 0; jg < 4; jg++) {
        ull a0 = 0, a1 = 0, a2 = 0, a3 = 0, a4 = 0, a5 = 0, a6 = 0, a7 = 0;
#pragma unroll
        for (int k = 0; k < 32; k++) {
            int base = k * 16 + jg * 4;
            ulonglong2 w01 = Wb[base], w23 = Wb[base+1], w45 = Wb[base+2], w67 = Wb[base+3];
            a0 = fma2(m[k], w01.x, a0); a1 = fma2(m[k], w01.y, a1);
            a2 = fma2(m[k], w23.x, a2); a3 = fma2(m[k], w23.y, a3);
            a4 = fma2(m[k], w45.x, a4); a5 = fma2(m[k], w45.y, a5);
            a6 = fma2(m[k], w67.x, a6); a7 = fma2(m[k], w67.y, a7);
        }
        float A0,A1,A2,A3,A4,A5,A6,A7,B0,B1,B2,B3,B4,B5,B6,B7;
        upk2(a0, A0, B0); upk2(a1, A1, B1); upk2(a2, A2, B2); upk2(a3, A3, B3);
        upk2(a4, A4, B4); upk2(a5, A5, B5); upk2(a6, A6, B6); upk2(a7, A7, B7);
        float4* oa = (float4*)(out + r * 32 + jg * 8);
        float4* ob = (float4*)(out + r * 32 + 32 + jg * 8);
        oa[0] = make_float4(A0, A1, A2, A3); oa[1] = make_float4(A4, A5, A6, A7);
        ob[0] = make_float4(B0, B1, B2, B3); ob[1] = make_float4(B4, B5, B6, B7);
    }
}

// ---------------- fused final layer + graph pooling ----------------
__global__ void __launch_bounds__(400) k_linpool(const float* __restrict__ in,
                                                 const float* __restrict__ W,
                                                 const float* __restrict__ bias,
                                                 float* __restrict__ xg) {
    __shared__ float2 sW[1024];
    __shared__ ull sB[32];
    __shared__ float sbuf[32 * 401];
    int t = threadIdx.x;
    for (int i = t; i < 1024; i += 400) { float w = W[i]; sW[i] = make_float2(w, w); }
    if (t < 32) { float b = bias[t]; sB[t] = pk2(b, b); }
    __syncthreads();
    size_t r = ((size_t)blockIdx.x * 400 + t) * 2;
    ull h[32];
    {
        const float4* ra = (const float4*)(in + r * 32);
        const float4* rb = (const float4*)(in + r * 32 + 32);
#pragma unroll
        for (int q = 0; q < 8; q++) {
            float4 a = __ldcs(ra + q), b = __ldcs(rb + q);
            h[4*q+0] = pk2(a.x, b.x); h[4*q+1] = pk2(a.y, b.y);
            h[4*q+2] = pk2(a.z, b.z); h[4*q+3] = pk2(a.w, b.w);
        }
    }
    const ulonglong2* Wv = (const ulonglong2*)sW;
#pragma unroll
    for (int jg = 0; jg < 4; jg++) {
        ull a0 = sB[jg*8+0], a1 = sB[jg*8+1], a2 = sB[jg*8+2], a3 = sB[jg*8+3];
        ull a4 = sB[jg*8+4], a5 = sB[jg*8+5], a6 = sB[jg*8+6], a7 = sB[jg*8+7];
#pragma unroll
        for (int k = 0; k < 32; k++) {
            int base = k * 16 + jg * 4;
            ulonglong2 w01 = Wv[base], w23 = Wv[base+1], w45 = Wv[base+2], w67 = Wv[base+3];
            a0 = fma2(h[k], w01.x, a0); a1 = fma2(h[k], w01.y, a1);
            a2 = fma2(h[k], w23.x, a2); a3 = fma2(h[k], w23.y, a3);
            a4 = fma2(h[k], w45.x, a4); a5 = fma2(h[k], w45.y, a5);
            a6 = fma2(h[k], w67.x, a6); a7 = fma2(h[k], w67.y, a7);
        }
        float lo, hi;
        upk2(a0, lo, hi); sbuf[(jg*8+0)*401 + t] = fmaxf(lo,0.f) + fmaxf(hi,0.f);
        upk2(a1, lo, hi); sbuf[(jg*8+1)*401 + t] = fmaxf(lo,0.f) + fmaxf(hi,0.f);
        upk2(a2, lo, hi); sbuf[(jg*8+2)*401 + t] = fmaxf(lo,0.f) + fmaxf(hi,0.f);
        upk2(a3, lo, hi); sbuf[(jg*8+3)*401 + t] = fmaxf(lo,0.f) + fmaxf(hi,0.f);
        upk2(a4, lo, hi); sbuf[(jg*8+4)*401 + t] = fmaxf(lo,0.f) + fmaxf(hi,0.f);
        upk2(a5, lo, hi); sbuf[(jg*8+5)*401 + t] = fmaxf(lo,0.f) + fmaxf(hi,0.f);
        upk2(a6, lo, hi); sbuf[(jg*8+6)*401 + t] = fmaxf(lo,0.f) + fmaxf(hi,0.f);
        upk2(a7, lo, hi); sbuf[(jg*8+7)*401 + t] = fmaxf(lo,0.f) + fmaxf(hi,0.f);
    }
    __syncthreads();
    for (int o = t; o < 512; o += 400) {
        int g = o >> 5, j = o & 31;
        const float* p = &sbuf[j * 401 + g * 25];
        float s = 0.f;
#pragma unroll
        for (int q = 0; q < 25; q++) s += p[q];
        xg[(size_t)blockIdx.x * 512 + o] = s;
    }
}

// ---------------- decoder first layer (transposed output) ----------------
__global__ void __launch_bounds__(256) k_declin(
    const float* __restrict__ in, const float* __restrict__ W,
    const float* __restrict__ bias, float* __restrict__ out) {
    __shared__ float sW[1024];
    __shared__ float sb[32];
    int t = threadIdx.x;
    for (int i = t; i < 1024; i += 256) sW[i] = W[i];
    if (t < 32) sb[t] = bias[t];
    __syncthreads();
    int r = (blockIdx.x * 256 + t) * 2;
    if (r >= BATCH) return;
    float hA[32], hB[32];
    const float4* ia = (const float4*)(in + (size_t)r * 32);
    const float4* ib = (const float4*)(in + (size_t)(r + 1) * 32);
#pragma unroll
    for (int q = 0; q < 8; q++) {
        float4 v = ia[q];
        hA[4*q] = v.x; hA[4*q+1] = v.y; hA[4*q+2] = v.z; hA[4*q+3] = v.w;
        float4 w = ib[q];
        hB[4*q] = w.x; hB[4*q+1] = w.y; hB[4*q+2] = w.z; hB[4*q+3] = w.w;
    }
#pragma unroll 2
    for (int j = 0; j < 32; j++) {
        float a = sb[j], b = sb[j];
#pragma unroll
        for (int k = 0; k < 32; k++) {
            float w = sW[k * 32 + j];
            a += hA[k] * w;
            b += hB[k] * w;
        }
        out[(size_t)j * BATCH + r]     = fmaxf(a, 0.f);
        out[(size_t)j * BATCH + r + 1] = fmaxf(b, 0.f);
    }
}

// ---------------- decoder weight/bias diff + pair tables ----------------
__global__ void k_initdec(const float* __restrict__ W1d, const float* __restrict__ b1d) {
    int idx = blockIdx.x * blockDim.x + threadIdx.x;
    if (idx >= 32 * NPAIRC) return;
    int k = idx / NPAIRC, p = idx - k * NPAIRC;
    g_wT[idx] = W1d[k * 2 * NPAIRC + 2 * p] - W1d[k * 2 * NPAIRC + 2 * p + 1];
    if (k == 0) {
        int i = 0, rem = p;
        while (rem >= NPG - 1 - i) { rem -= NPG - 1 - i; i++; }
        g_iu[p] = i;
        g_ju[p] = i + 1 + rem;
        g_db[p] = b1d[2 * p] - b1d[2 * p + 1];
    }
}

// ---------------- fused decoder GEMM + gumbel hard-argmax ----------------
__global__ void __launch_bounds__(256) k_decgemm(const float* __restrict__ gn) {
    __shared__ float sd[2048];
    __shared__ float sw[2048];
    __shared__ float sdb[64];
    __shared__ float sout[4096];
    int t = threadIdx.x;
    int g0 = blockIdx.x * 64, p0 = blockIdx.y * 64;
    for (int i = t; i < 2048; i += 256) {
        int k = i >> 6, c = i & 63;
        sd[i] = g_dT[(size_t)k * BATCH + g0 + c];
        int p = p0 + c;
        sw[i] = (p < NPAIRC) ? g_wT[k * NPAIRC + p] : 0.f;
    }
    if (t < 64) sdb[t] = (p0 + t < NPAIRC) ? g_db[p0 + t] : 0.f;
    __syncthreads();
    int gi = (t & 15) * 4, pi = (t >> 4) * 4;
    float acc[4][4];
#pragma unroll
    for (int r = 0; r < 4; r++)
#pragma unroll
        for (int c = 0; c < 4; c++) acc[r][c] = 0.f;
#pragma unroll 8
    for (int k = 0; k < 32; k++) {
        float4 a = *(float4*)&sd[k * 64 + gi];
        float4 w = *(float4*)&sw[k * 64 + pi];
        acc[0][0] += a.x * w.x; acc[0][1] += a.x * w.y; acc[0][2] += a.x * w.z; acc[0][3] += a.x * w.w;
        acc[1][0] += a.y * w.x; acc[1][1] += a.y * w.y; acc[1][2] += a.y * w.z; acc[1][3] += a.y * w.w;
        acc[2][0] += a.z * w.x; acc[2][1] += a.z * w.y; acc[2][2] += a.z * w.z; acc[2][3] += a.z * w.w;
        acc[3][0] += a.w * w.x; acc[3][1] += a.w * w.y; acc[3][2] += a.w * w.z; acc[3][3] += a.w * w.w;
    }
#pragma unroll
    for (int r = 0; r < 4; r++)
        *(float4*)&sout[(gi + r) * 64 + pi] = make_float4(acc[r][0], acc[r][1], acc[r][2], acc[r][3]);
    __syncthreads();
    for (int i = t; i < 4096; i += 256) {
        int g = i >> 6, p = i & 63;
        int pp = p0 + p;
        if (pp < NPAIRC) {
            float2 gv = __ldcs((const float2*)gn + (size_t)(g0 + g) * NPAIRC + pp);
            float m = sout[i] + sdb[p] + gv.x - gv.y;
            g_vals[(size_t)(g0 + g) * NPAIRC + pp] = (m >= 0.f) ? 1 : 0;
        }
    }
}

// ---------------- symmetric adjacency assembly ----------------
__global__ void k_assembly(float* __restrict__ out) {
    __shared__ float tile[2500];
    int t = threadIdx.x;
    int b = blockIdx.x;
    for (int i = t; i < 2500; i += 256) tile[i] = 0.f;
    __syncthreads();
    const unsigned char* vr = g_vals + (size_t)b * NPAIRC;
    for (int p = t; p < NPAIRC; p += 256) {
        float v = vr[p] ? 1.f : 0.f;
        int i = g_iu[p], j = g_ju[p];
        tile[i * NPG + j] = v;
        tile[j * NPG + i] = v;
    }
    __syncthreads();
    float4* o4 = (float4*)(out + (size_t)b * 2500);
    const float4* t4 = (const float4*)tile;
    for (int i = t; i < 625; i += 256) {
        float4 v = t4[i];
        __stcs(o4 + i, v);
    }
}

// ---------------- host orchestration ----------------
extern "C" void kernel_launch(void* const* d_in, const int* in_sizes, int n_in,
                              void* d_out, int out_size) {
    const float* x    = (const float*)d_in[0];
    const int*   ei   = (const int*)  d_in[1];
    const float* gn   = (const float*)d_in[3];
    const float* e0W1 = (const float*)d_in[4];
    const float* e0b1 = (const float*)d_in[5];
    const float* e0g  = (const float*)d_in[6];
    const float* e0be = (const float*)d_in[7];
    const float* e0W2 = (const float*)d_in[8];
    const float* e0b2 = (const float*)d_in[9];
    const float* e1W1 = (const float*)d_in[10];
    const float* e1b1 = (const float*)d_in[11];
    const float* e1g  = (const float*)d_in[12];
    const float* e1be = (const float*)d_in[13];
    const float* e1W2 = (const float*)d_in[14];
    const float* e1b2 = (const float*)d_in[15];
    const float* dW0  = (const float*)d_in[16];
    const float* db0  = (const float*)d_in[17];
    const float* dW1  = (const float*)d_in[18];
    const float* db1  = (const float*)d_in[19];
    float* out = (float*)d_out;

    void *p_bufA, *p_bufB, *p_part0, *p_part1, *p_w2e, *p_b2e, *p_w2e2, *p_b2e2, *p_xg, *p_dT;
    cudaGetSymbolAddress(&p_bufA, g_bufA);
    cudaGetSymbolAddress(&p_bufB, g_bufB);
    cudaGetSymbolAddress(&p_part0, g_part0);
    cudaGetSymbolAddress(&p_part1, g_part1);
    cudaGetSymbolAddress(&p_w2e, g_W2eff);
    cudaGetSymbolAddress(&p_b2e, g_b2eff);
    cudaGetSymbolAddress(&p_w2e2, g_W2eff2);
    cudaGetSymbolAddress(&p_b2e2, g_b2eff2);
    cudaGetSymbolAddress(&p_xg, g_xg);
    cudaGetSymbolAddress(&p_dT, g_dT);
    float* bufA = (float*)p_bufA;
    float* bufB = (float*)p_bufB;

    const int TB = 256;

    // fork a second captured stream for work independent of the CSR build
    cudaStream_t s2;
    cudaStreamCreateWithFlags(&s2, cudaStreamNonBlocking);
    cudaEvent_t eF, eJ;
    cudaEventCreateWithFlags(&eF, cudaEventDisableTiming);
    cudaEventCreateWithFlags(&eJ, cudaEventDisableTiming);
    cudaEventRecord(eF, 0);
    cudaStreamWaitEvent(s2, eF, 0);
    k_initdec<<<(32 * NPAIRC + TB - 1) / TB, TB, 0, s2>>>(dW1, db1);
    k_z0<<<N_NODES / TB, TB, 0, s2>>>(x, e0W1, bufA);
    cudaEventRecord(eJ, s2);

    // main stream: zero + CSR build
    k_zero<<<801, TB>>>();
    k_deg<<<N_EDGES / 4 / TB, TB>>>(ei);
    k_scanA<<<800, 1024>>>();
    k_scanB<<<1, 1024>>>();
    k_scanC<<<800, 1024>>>();
    k_fill<<<N_EDGES / 4 / TB, TB>>>(ei);
    cudaStreamWaitEvent(0, eJ, 0);

    // layer 0
    k_gather<<<N_NODES / 64, TB>>>(bufA, e0b1, bufB, (float*)p_part0);
    k_bnfuse<<<1, 32>>>((float*)p_part0, e0g, e0be, e0W2, e0b2, (float*)p_w2e, (float*)p_b2e);
    k_mid<<<N_NODES / 512, TB>>>(bufB, (float*)p_w2e, (float*)p_b2e, e1W1, bufA);
    // layer 1
    k_gather<<<N_NODES / 64, TB>>>(bufA, e1b1, bufB, (float*)p_part1);
    k_bnfuse<<<1, 32>>>((float*)p_part1, e1g, e1be, e1W2, e1b2, (float*)p_w2e2, (float*)p_b2e2);
    k_linpool<<<N_NODES / 800, 400>>>(bufB, (float*)p_w2e2, (float*)p_b2e2, (float*)p_xg);
    // decoder
    k_declin<<<BATCH / 512, TB>>>((float*)p_xg, dW0, db0, (float*)p_dT);
    dim3 gg(BATCH / 64, (NPAIRC + 63) / 64);
    k_decgemm<<<gg, TB>>>(gn);
    k_assembly<<<BATCH, TB>>>(out);
    (void)in_sizes; (void)n_in; (void)out_size;
}